// round 15
// baseline (speedup 1.0000x reference)
#include <cuda_runtime.h>
#include <cuda_bf16.h>
#include <math.h>
#include <stdint.h>
#include <string.h>

// Problem constants
#define BB 2
#define SS 2048
#define DD 1024
#define HH 16
#define DHH 64
#define MM 4096
#define ROWS (BB*SS)          // 4096
#define EPS 1e-6f

// HMMA GEMM tiling (128x64 tile, 3-stage, swizzled 64B rows: 3 CTAs/SM)
#define BMH 128
#define BNH 64
#define BKH 32
#define LDSROW 64                 // bytes per smem row (32 bf16, XOR-swizzled)
#define TILEA (128*LDSROW)        // 8192 bytes (A matrix tile)
#define TILEBB (64*LDSROW)        // 4096 bytes (B matrix tile)
#define STAGE_H (2*TILEA + 2*TILEBB)  // Ah, Al, Bh, Bl = 24576
#define HSMEM (3*STAGE_H)         // 73728 (3 stages, 3 CTAs/SM)

// Flash attention tiling (3-stage, SW128-swizzled 128B rows, Q-region reuse)
#define AQT 128                   // q rows per block
#define AKT 64                    // keys per tile
#define AMAT 8192                 // one matrix tile: 64 rows * 128B
#define ASTAGE (4*AMAT)           // Kh,Kl,Vh,Vl = 32768
#define ASMEM (3*ASTAGE)          // 98304: Q region doubles as stage 2 (offset 0)

// GEMM smem swizzle: 64B rows, 4 chunks of 16B; chunk' = chunk ^ ((row>>1)&3)
#define GSWZ(row, seg) ((seg) ^ (((row) >> 1) & 3))
// Attention smem swizzle: 128B rows, 8 chunks of 16B; chunk' = chunk ^ (row&7)
#define ASWZ(row, seg) ((seg) ^ ((row) & 7))

// ---------------- scratch (static device globals; no allocations) -----------
__device__ __nv_bfloat16 g_h_hi[ROWS*DD],  g_h_lo[ROWS*DD];
__device__ __nv_bfloat16 g_qh[ROWS*DD], g_ql[ROWS*DD];
__device__ __nv_bfloat16 g_kh[ROWS*DD], g_kl[ROWS*DD];
__device__ __nv_bfloat16 g_vh[ROWS*DD], g_vl[ROWS*DD];
__device__ __nv_bfloat16 g_ctx_hi[ROWS*DD], g_ctx_lo[ROWS*DD];
__device__ float         g_mlpin[ROWS*DD];
__device__ __nv_bfloat16 g_h2_hi[ROWS*DD], g_h2_lo[ROWS*DD];
__device__ __nv_bfloat16 g_mid_hi[ROWS*MM], g_mid_lo[ROWS*MM];
__device__ float         g_rope[SS*64];    // [s][2i]=cos, [s][2i+1]=sin
// transposed bf16 weights [N][K]; qkv stacked [3*DD][DD]
__device__ __nv_bfloat16 g_wqkvt_h[3*DD*DD], g_wqkvt_l[3*DD*DD];
__device__ __nv_bfloat16 g_wot_h[DD*DD], g_wot_l[DD*DD];
__device__ __nv_bfloat16 g_w1t_h[MM*DD], g_w1t_l[MM*DD];
__device__ __nv_bfloat16 g_w2t_h[DD*MM], g_w2t_l[DD*MM];

// ---------------- helpers ----------------------------------------------------
__device__ __forceinline__ uint32_t smem_to_u32(const void* p) {
    uint32_t a;
    asm("{ .reg .u64 t; cvta.to.shared.u64 t, %1; cvt.u32.u64 %0, t; }" : "=r"(a) : "l"(p));
    return a;
}
__device__ __forceinline__ void cp16(uint32_t saddr, const void* gaddr) {
    asm volatile("cp.async.cg.shared.global [%0], [%1], 16;" :: "r"(saddr), "l"(gaddr) : "memory");
}
__device__ __forceinline__ void cp_commit() {
    asm volatile("cp.async.commit_group;" ::: "memory");
}
__device__ __forceinline__ void cp_wait1() {
    asm volatile("cp.async.wait_group 1;" ::: "memory");
}
__device__ __forceinline__ void ldmx4(uint32_t* d, uint32_t addr) {
    asm volatile("ldmatrix.sync.aligned.m8n8.x4.shared.b16 {%0,%1,%2,%3}, [%4];"
                 : "=r"(d[0]), "=r"(d[1]), "=r"(d[2]), "=r"(d[3]) : "r"(addr));
}
__device__ __forceinline__ void ldmx4t(uint32_t* d, uint32_t addr) {
    asm volatile("ldmatrix.sync.aligned.m8n8.x4.trans.shared.b16 {%0,%1,%2,%3}, [%4];"
                 : "=r"(d[0]), "=r"(d[1]), "=r"(d[2]), "=r"(d[3]) : "r"(addr));
}
__device__ __forceinline__ void mma_bf16(float* c, const uint32_t* a, const uint32_t* b) {
    asm volatile("mma.sync.aligned.m16n8k16.row.col.f32.bf16.bf16.f32 "
                 "{%0,%1,%2,%3}, {%4,%5,%6,%7}, {%8,%9}, {%0,%1,%2,%3};"
                 : "+f"(c[0]), "+f"(c[1]), "+f"(c[2]), "+f"(c[3])
                 : "r"(a[0]), "r"(a[1]), "r"(a[2]), "r"(a[3]), "r"(b[0]), "r"(b[1]));
}
__device__ __forceinline__ void split_bf16(float v, __nv_bfloat16& h, __nv_bfloat16& l) {
    h = __float2bfloat16(v);
    l = __float2bfloat16(v - __bfloat162float(h));
}
__device__ __forceinline__ uint32_t pack_bf2(float a, float b) {
    __nv_bfloat162 t = __floats2bfloat162_rn(a, b);
    return *reinterpret_cast<uint32_t*>(&t);
}
// fast tanh-gelu via sigmoid identity
__device__ __forceinline__ float gelu_f(float x) {
    float u2 = 1.5957691216057308f * (x + 0.044715f * x * x * x);
    float e = __expf(u2);
    return x * (1.0f - __fdividef(1.0f, e + 1.0f));
}

// ---------------- RoPE cos/sin table -----------------------------------------
__global__ void rope_tab(float* __restrict__ tab)
{
    int idx = blockIdx.x * 256 + threadIdx.x;
    int s = idx >> 5, i = idx & 31;
    float freq = powf(10000.0f, -((float)(2*i)) / 64.0f);
    float ang = (float)s * freq;
    float sn, cs;
    sincosf(ang, &sn, &cs);
    tab[s*64 + 2*i]     = cs;
    tab[s*64 + 2*i + 1] = sn;
}

// ---------------- LayerNorm -> bf16 hi/lo (vectorized) ------------------------
__global__ void ln_bf16(const float* __restrict__ x,
                        const float* __restrict__ gamma,
                        const float* __restrict__ beta,
                        __nv_bfloat16* __restrict__ oh,
                        __nv_bfloat16* __restrict__ ol)
{
    __shared__ float red0[8], red1[8];
    int row = blockIdx.x;
    int t = threadIdx.x;
    const float* xr = x + (size_t)row * DD;
    float4 xv = *(const float4*)(xr + 4*t);
    float sum = xv.x + xv.y + xv.z + xv.w;
    float sq  = xv.x*xv.x + xv.y*xv.y + xv.z*xv.z + xv.w*xv.w;
#pragma unroll
    for (int o = 16; o; o >>= 1) {
        sum += __shfl_xor_sync(0xffffffffu, sum, o);
        sq  += __shfl_xor_sync(0xffffffffu, sq,  o);
    }
    if ((t & 31) == 0) { red0[t >> 5] = sum; red1[t >> 5] = sq; }
    __syncthreads();
    if (t < 32) {
        float s = (t < 8) ? red0[t] : 0.f;
        float q = (t < 8) ? red1[t] : 0.f;
#pragma unroll
        for (int o = 4; o; o >>= 1) {
            s += __shfl_xor_sync(0xffffffffu, s, o);
            q += __shfl_xor_sync(0xffffffffu, q, o);
        }
        if (t == 0) { red0[0] = s; red1[0] = q; }
    }
    __syncthreads();
    float mean = red0[0] * (1.f / (float)DD);
    float var  = red1[0] * (1.f / (float)DD) - mean*mean;
    float rstd = rsqrtf(var + EPS);
    float4 gv = *(const float4*)(gamma + 4*t);
    float4 bv = *(const float4*)(beta + 4*t);
    float v0 = (xv.x - mean) * rstd * gv.x + bv.x;
    float v1 = (xv.y - mean) * rstd * gv.y + bv.y;
    float v2 = (xv.z - mean) * rstd * gv.z + bv.z;
    float v3 = (xv.w - mean) * rstd * gv.w + bv.w;
    __nv_bfloat162 h01 = __floats2bfloat162_rn(v0, v1);
    __nv_bfloat162 h23 = __floats2bfloat162_rn(v2, v3);
    __nv_bfloat162 l01 = __floats2bfloat162_rn(v0 - __low2float(h01), v1 - __high2float(h01));
    __nv_bfloat162 l23 = __floats2bfloat162_rn(v2 - __low2float(h23), v3 - __high2float(h23));
    size_t base = (size_t)row * DD + 4*t;
    uint2 hp = make_uint2(*reinterpret_cast<uint32_t*>(&h01), *reinterpret_cast<uint32_t*>(&h23));
    uint2 lp = make_uint2(*reinterpret_cast<uint32_t*>(&l01), *reinterpret_cast<uint32_t*>(&l23));
    *reinterpret_cast<uint2*>(oh + base) = hp;
    *reinterpret_cast<uint2*>(ol + base) = lp;
}

// ---------------- merged weight transpose + split (all 6 weights) ------------
__global__ void tconv_all(const float* __restrict__ wq, const float* __restrict__ wk,
                          const float* __restrict__ wv, const float* __restrict__ wo,
                          const float* __restrict__ w1, const float* __restrict__ w2,
                          __nv_bfloat16* __restrict__ wqkvt_h, __nv_bfloat16* __restrict__ wqkvt_l,
                          __nv_bfloat16* __restrict__ wot_h,  __nv_bfloat16* __restrict__ wot_l,
                          __nv_bfloat16* __restrict__ w1t_h,  __nv_bfloat16* __restrict__ w1t_l,
                          __nv_bfloat16* __restrict__ w2t_h,  __nv_bfloat16* __restrict__ w2t_l)
{
    __shared__ float t[32][33];
    int bid = blockIdx.x;
    const float* W; __nv_bfloat16 *Th, *Tl;
    int K, N, tile;
    if (bid < 4096) {
        int w = bid >> 10; tile = bid & 1023;
        K = DD; N = DD;
        if (w == 0)      { W = wq; Th = wqkvt_h;           Tl = wqkvt_l; }
        else if (w == 1) { W = wk; Th = wqkvt_h + DD*DD;   Tl = wqkvt_l + DD*DD; }
        else if (w == 2) { W = wv; Th = wqkvt_h + 2*DD*DD; Tl = wqkvt_l + 2*DD*DD; }
        else             { W = wo; Th = wot_h;             Tl = wot_l; }
    } else if (bid < 8192) {
        tile = bid - 4096; K = DD; N = MM;
        W = w1; Th = w1t_h; Tl = w1t_l;
    } else {
        tile = bid - 8192; K = MM; N = DD;
        W = w2; Th = w2t_h; Tl = w2t_l;
    }
    int ntx = N >> 5;
    int n0 = (tile % ntx) * 32, k0 = (tile / ntx) * 32;
    int tx = threadIdx.x, ty = threadIdx.y;
#pragma unroll
    for (int j = 0; j < 32; j += 8)
        t[ty + j][tx] = W[(size_t)(k0 + ty + j) * N + n0 + tx];
    __syncthreads();
#pragma unroll
    for (int j = 0; j < 32; j += 8) {
        float v = t[tx][ty + j];
        __nv_bfloat16 hh, ll; split_bf16(v, hh, ll);
        size_t o = (size_t)(n0 + ty + j) * K + k0 + tx;
        Th[o] = hh; Tl[o] = ll;
    }
}

// ---------------- shared GEMM machinery (128x64 tile, 3-stage) ----------------
struct GemmAcc { float a[2][4][4]; };

__device__ __forceinline__ void gemm_mainloop(
    uint32_t sb, int tid, int wid, int lane,
    const __nv_bfloat16* Ahb, const __nv_bfloat16* Alb,
    const __nv_bfloat16* Bhb, const __nv_bfloat16* Blb,
    int Kdim, GemmAcc& acc)
{
    int nch = Kdim / BKH;
    int wm = (wid & 3) * 32;     // 4 m-subtiles
    int wn = (wid >> 2) * 32;    // 2 n-subtiles

    auto load_chunk = [&](int c, int s) {
        int k0 = c * BKH;
        uint32_t st = sb + s * STAGE_H;
        // A: 128 rows x 4 segs = 512 quads; B: 64 rows x 4 segs = 256 quads
#pragma unroll
        for (int i = tid; i < 512; i += 256) {
            int row = i >> 2, seg = i & 3;
            uint32_t so = st + row * LDSROW + GSWZ(row, seg) * 16;
            size_t go = (size_t)row * Kdim + k0 + seg * 8;
            cp16(so,           Ahb + go);
            cp16(so + TILEA,   Alb + go);
            if (i < 256) {
                uint32_t sob = st + 2*TILEA + row * LDSROW + GSWZ(row, seg) * 16;
                cp16(sob,          Bhb + go);
                cp16(sob + TILEBB, Blb + go);
            }
        }
    };

    load_chunk(0, 0);
    cp_commit();
    load_chunk(1, 1);
    cp_commit();

    for (int c = 0; c < nch; c++) {
        int s = c % 3;
        cp_wait1();
        __syncthreads();
        if (c + 2 < nch) load_chunk(c + 2, (c + 2) % 3);
        cp_commit();

        uint32_t st = sb + s * STAGE_H;
#pragma unroll
        for (int ks = 0; ks < 2; ks++) {
            int colb = ks * 16 + (lane >> 4) * 8;
            uint32_t ah[2][4], al[2][4];
#pragma unroll
            for (int mf = 0; mf < 2; mf++) {
                int r = wm + mf * 16 + (lane & 15);
                uint32_t ad = st + r * LDSROW + GSWZ(r, colb >> 3) * 16;
                ldmx4(ah[mf], ad);
                ldmx4(al[mf], ad + TILEA);
            }
#pragma unroll
            for (int nf2 = 0; nf2 < 2; nf2++) {
                int r = wn + nf2 * 16 + ((lane >> 3) & 1) * 8 + (lane & 7);
                uint32_t bd = st + 2*TILEA + r * LDSROW + GSWZ(r, colb >> 3) * 16;
                uint32_t tb[4], bh0[2], bh1[2], bl0[2], bl1[2];
                ldmx4(tb, bd);
                bh0[0] = tb[0]; bh0[1] = tb[2]; bh1[0] = tb[1]; bh1[1] = tb[3];
                ldmx4(tb, bd + TILEBB);
                bl0[0] = tb[0]; bl0[1] = tb[2]; bl1[0] = tb[1]; bl1[1] = tb[3];
#pragma unroll
                for (int mf = 0; mf < 2; mf++) {
                    mma_bf16(acc.a[mf][nf2*2],   ah[mf], bh0);
                    mma_bf16(acc.a[mf][nf2*2],   ah[mf], bl0);
                    mma_bf16(acc.a[mf][nf2*2],   al[mf], bh0);
                    mma_bf16(acc.a[mf][nf2*2+1], ah[mf], bh1);
                    mma_bf16(acc.a[mf][nf2*2+1], ah[mf], bl1);
                    mma_bf16(acc.a[mf][nf2*2+1], al[mf], bh1);
                }
            }
        }
    }
}

// ---------------- generic GEMM kernel ----------------------------------------
// modes: 1 C=acc+resid; 2 Oh/Ol=split(gelu(acc+bias)); 3 C=acc+bias+resid
__global__ __launch_bounds__(256, 3)
void gemm_hmma(const __nv_bfloat16* __restrict__ Ah, const __nv_bfloat16* __restrict__ Al,
               const __nv_bfloat16* __restrict__ Bh, const __nv_bfloat16* __restrict__ Bl,
               float* __restrict__ C, int Ndim, int Kdim,
               const float* __restrict__ bias, const float* __restrict__ resid,
               __nv_bfloat16* __restrict__ Oh, __nv_bfloat16* __restrict__ Ol,
               int mode)
{
    extern __shared__ char hs[];
    uint32_t sb = smem_to_u32(hs);
    int tid = threadIdx.x, wid = tid >> 5, lane = tid & 31;
    int bx = blockIdx.x, by = blockIdx.y;

    GemmAcc acc;
#pragma unroll
    for (int i = 0; i < 2; i++)
#pragma unroll
        for (int j = 0; j < 4; j++)
#pragma unroll
            for (int r = 0; r < 4; r++) acc.a[i][j][r] = 0.f;

    gemm_mainloop(sb, tid, wid, lane,
                  Ah + (size_t)by * BMH * Kdim, Al + (size_t)by * BMH * Kdim,
                  Bh + (size_t)bx * BNH * Kdim, Bl + (size_t)bx * BNH * Kdim,
                  Kdim, acc);

    int wm = (wid & 3) * 32, wn = (wid >> 2) * 32;
    int g = lane >> 2, qd = lane & 3;
#pragma unroll
    for (int mf = 0; mf < 2; mf++) {
#pragma unroll
        for (int half = 0; half < 2; half++) {
            int grow = by * BMH + wm + mf * 16 + g + half * 8;
#pragma unroll
            for (int nf = 0; nf < 4; nf++) {
                int gcol = bx * BNH + wn + nf * 8 + qd * 2;
                float v0 = acc.a[mf][nf][half*2 + 0];
                float v1 = acc.a[mf][nf][half*2 + 1];
                size_t o = (size_t)grow * Ndim + gcol;
                if (mode == 1) {
                    C[o] = v0 + resid[o]; C[o+1] = v1 + resid[o+1];
                } else if (mode == 2) {
                    float g0 = gelu_f(v0 + bias[gcol]);
                    float g1 = gelu_f(v1 + bias[gcol+1]);
                    __nv_bfloat16 hh, ll;
                    split_bf16(g0, hh, ll); Oh[o] = hh; Ol[o] = ll;
                    split_bf16(g1, hh, ll); Oh[o+1] = hh; Ol[o+1] = ll;
                } else {
                    C[o]   = v0 + bias[gcol]   + resid[o];
                    C[o+1] = v1 + bias[gcol+1] + resid[o+1];
                }
            }
        }
    }
}

// ---------------- fused QKV GEMM with in-register RoPE -----------------------
// Wh/Wl: stacked [3*DD][DD] (wq; wk; wv). bx in [0,48): mat = bx>>4, bn = bx&15.
__global__ __launch_bounds__(256, 3)
void gemm_qkv(const __nv_bfloat16* __restrict__ Ah, const __nv_bfloat16* __restrict__ Al,
              const __nv_bfloat16* __restrict__ Wh, const __nv_bfloat16* __restrict__ Wl,
              const float* __restrict__ rope,
              __nv_bfloat16* __restrict__ qh, __nv_bfloat16* __restrict__ ql,
              __nv_bfloat16* __restrict__ kh, __nv_bfloat16* __restrict__ kl,
              __nv_bfloat16* __restrict__ vh, __nv_bfloat16* __restrict__ vl)
{
    extern __shared__ char hs[];
    uint32_t sb = smem_to_u32(hs);
    int tid = threadIdx.x, wid = tid >> 5, lane = tid & 31;
    int bx = blockIdx.x, by = blockIdx.y;
    int mat = bx >> 4, bn = bx & 15;

    GemmAcc acc;
#pragma unroll
    for (int i = 0; i < 2; i++)
#pragma unroll
        for (int j = 0; j < 4; j++)
#pragma unroll
            for (int r = 0; r < 4; r++) acc.a[i][j][r] = 0.f;

    size_t woff = ((size_t)mat * DD + (size_t)bn * BNH) * DD;
    gemm_mainloop(sb, tid, wid, lane,
                  Ah + (size_t)by * BMH * DD, Al + (size_t)by * BMH * DD,
                  Wh + woff, Wl + woff, DD, acc);

    __nv_bfloat16* Oh = (mat == 0) ? qh : (mat == 1) ? kh : vh;
    __nv_bfloat16* Ol = (mat == 0) ? ql : (mat == 1) ? kl : vl;
    float qscale = (mat == 0) ? 0.125f : 1.0f;

    int wm = (wid & 3) * 32, wn = (wid >> 2) * 32;
    int g = lane >> 2, qd = lane & 3;
#pragma unroll
    for (int mf = 0; mf < 2; mf++) {
#pragma unroll
        for (int half = 0; half < 2; half++) {
            int grow = by * BMH + wm + mf * 16 + g + half * 8;
            int srow = grow & (SS - 1);
#pragma unroll
            for (int nf = 0; nf < 4; nf++) {
                int gcol = bn * BNH + wn + nf * 8 + qd * 2;
                float v0 = acc.a[mf][nf][half*2 + 0];
                float v1 = acc.a[mf][nf][half*2 + 1];
                size_t o = (size_t)grow * DD + gcol;
                if (mat < 2) {
                    int i2 = gcol & 63;
                    float2 cs = *(const float2*)(rope + (size_t)srow * 64 + i2);
                    float r0 = (v0 * cs.x - v1 * cs.y) * qscale;
                    float r1 = (v0 * cs.y + v1 * cs.x) * qscale;
                    __nv_bfloat16 hh, ll;
                    split_bf16(r0, hh, ll); Oh[o] = hh; Ol[o] = ll;
                    split_bf16(r1, hh, ll); Oh[o+1] = hh; Ol[o+1] = ll;
                } else {
                    __nv_bfloat16 hh, ll;
                    split_bf16(v0, hh, ll); Oh[o] = hh; Ol[o] = ll;
                    split_bf16(v1, hh, ll); Oh[o+1] = hh; Ol[o+1] = ll;
                }
            }
        }
    }
}

// ---------------- HMMA flash attention (bf16x3, 3-stage, Q-region reuse) -----
__global__ __launch_bounds__(256, 2)
void flash_attn_hmma(const __nv_bfloat16* __restrict__ qh, const __nv_bfloat16* __restrict__ ql,
                     const __nv_bfloat16* __restrict__ kh, const __nv_bfloat16* __restrict__ kl,
                     const __nv_bfloat16* __restrict__ vh, const __nv_bfloat16* __restrict__ vl,
                     __nv_bfloat16* __restrict__ ctx_hi, __nv_bfloat16* __restrict__ ctx_lo)
{
    extern __shared__ char fs[];
    uint32_t sb = smem_to_u32(fs);
    int tid = threadIdx.x, wid = tid >> 5, lane = tid & 31;
    int g = lane >> 2, qd = lane & 3;
    int qt = blockIdx.x, bh = blockIdx.y;
    int b = bh >> 4, h = bh & 15;
    int q0 = qt * AQT;

    const __nv_bfloat16* qhb = qh + ((size_t)(b*SS + q0)) * DD + h * DHH;
    const __nv_bfloat16* qlb = ql + ((size_t)(b*SS + q0)) * DD + h * DHH;
    const __nv_bfloat16* khb = kh + ((size_t)(b*SS)) * DD + h * DHH;
    const __nv_bfloat16* klb = kl + ((size_t)(b*SS)) * DD + h * DHH;
    const __nv_bfloat16* vhb = vh + ((size_t)(b*SS)) * DD + h * DHH;
    const __nv_bfloat16* vlb = vl + ((size_t)(b*SS)) * DD + h * DHH;

    auto load_tile = [&](int t) {
        uint32_t st = sb + ((t % 3 == 0) ? 32768u : (t % 3 == 1) ? 65536u : 0u);
        const __nv_bfloat16* srcs[4] = {khb, klb, vhb, vlb};
#pragma unroll
        for (int i = tid; i < 2048; i += 256) {
            int mtx = i >> 9;
            int j = i & 511;
            int row = j >> 3, seg = j & 7;
            uint32_t so = st + mtx * AMAT + row * 128 + ASWZ(row, seg) * 16;
            cp16(so, srcs[mtx] + (size_t)(t*AKT + row) * DD + seg * 8);
        }
    };

#pragma unroll
    for (int i = tid; i < 2048; i += 256) {
        int mtx = i >> 10;
        int j = i & 1023;
        int row = j >> 3, seg = j & 7;
        uint32_t so = sb + mtx * 16384 + row * 128 + ASWZ(row, seg) * 16;
        const __nv_bfloat16* src = (mtx ? qlb : qhb) + (size_t)row * DD + seg * 8;
        cp16(so, src);
    }
    load_tile(0);
    cp_commit();
    load_tile(1);
    cp_commit();

    float oacc[8][4];
#pragma unroll
    for (int i = 0; i < 8; i++)
#pragma unroll
        for (int j = 0; j < 4; j++) oacc[i][j] = 0.f;
    float m0 = -INFINITY, m1 = -INFINITY, l0 = 0.f, l1 = 0.f;
    uint32_t qfh[4][4], qfl[4][4];

    int ntiles = SS / AKT;   // 32
    for (int t = 0; t < ntiles; t++) {
        uint32_t stb = sb + ((t % 3 == 0) ? 32768u : (t % 3 == 1) ? 65536u : 0u);
        cp_wait1();
        __syncthreads();

        if (t == 0) {
#pragma unroll
            for (int ks = 0; ks < 4; ks++) {
                int r = wid * 16 + (lane & 15);
                int ch = ks * 2 + (lane >> 4);
                uint32_t ad = sb + r * 128 + ASWZ(r, ch) * 16;
                ldmx4(qfh[ks], ad);
                ldmx4(qfl[ks], ad + 16384);
            }
            __syncthreads();
        }

        if (t + 2 < ntiles) load_tile(t + 2);
        cp_commit();

        // ---- S = Q K^T ----
        float sacc[8][4];
#pragma unroll
        for (int i = 0; i < 8; i++)
#pragma unroll
            for (int j = 0; j < 4; j++) sacc[i][j] = 0.f;
#pragma unroll
        for (int ks = 0; ks < 4; ks++) {
#pragma unroll
            for (int nf2 = 0; nf2 < 4; nf2++) {
                int r = nf2 * 16 + ((lane >> 3) & 1) * 8 + (lane & 7);
                int ch = ks * 2 + (lane >> 4);
                uint32_t ad = stb + r * 128 + ASWZ(r, ch) * 16;
                uint32_t tb[4], kh0[2], kh1[2], kl0[2], kl1[2];
                ldmx4(tb, ad);
                kh0[0] = tb[0]; kh0[1] = tb[2]; kh1[0] = tb[1]; kh1[1] = tb[3];
                ldmx4(tb, ad + AMAT);
                kl0[0] = tb[0]; kl0[1] = tb[2]; kl1[0] = tb[1]; kl1[1] = tb[3];
                mma_bf16(sacc[nf2*2],   qfh[ks], kh0);
                mma_bf16(sacc[nf2*2],   qfh[ks], kl0);
                mma_bf16(sacc[nf2*2],   qfl[ks], kh0);
                mma_bf16(sacc[nf2*2+1], qfh[ks], kh1);
                mma_bf16(sacc[nf2*2+1], qfh[ks], kl1);
                mma_bf16(sacc[nf2*2+1], qfl[ks], kh1);
            }
        }

        // ---- online softmax on fragments ----
        float mx0 = -INFINITY, mx1 = -INFINITY;
#pragma unroll
        for (int nf = 0; nf < 8; nf++) {
            mx0 = fmaxf(mx0, fmaxf(sacc[nf][0], sacc[nf][1]));
            mx1 = fmaxf(mx1, fmaxf(sacc[nf][2], sacc[nf][3]));
        }
        mx0 = fmaxf(mx0, __shfl_xor_sync(0xffffffffu, mx0, 1));
        mx0 = fmaxf(mx0, __shfl_xor_sync(0xffffffffu, mx0, 2));
        mx1 = fmaxf(mx1, __shfl_xor_sync(0xffffffffu, mx1, 1));
        mx1 = fmaxf(mx1, __shfl_xor_sync(0xffffffffu, mx1, 2));
        float mnew0 = fmaxf(m0, mx0), mnew1 = fmaxf(m1, mx1);
        float corr0 = __expf(m0 - mnew0), corr1 = __expf(m1 - mnew1);

        uint32_t ph[4][4], pl[4][4];
        float ps0 = 0.f, ps1 = 0.f;
#pragma unroll
        for (int nf = 0; nf < 8; nf++) {
            float p0 = __expf(sacc[nf][0] - mnew0);
            float p1 = __expf(sacc[nf][1] - mnew0);
            float p2 = __expf(sacc[nf][2] - mnew1);
            float p3 = __expf(sacc[nf][3] - mnew1);
            ps0 += p0 + p1; ps1 += p2 + p3;
            __nv_bfloat162 h01 = __floats2bfloat162_rn(p0, p1);
            __nv_bfloat162 h23 = __floats2bfloat162_rn(p2, p3);
            float e0 = p0 - __low2float(h01), e1 = p1 - __high2float(h01);
            float e2 = p2 - __low2float(h23), e3 = p3 - __high2float(h23);
            int kks = nf >> 1, hf = nf & 1;
            ph[kks][hf*2 + 0] = *reinterpret_cast<uint32_t*>(&h01);
            ph[kks][hf*2 + 1] = *reinterpret_cast<uint32_t*>(&h23);
            pl[kks][hf*2 + 0] = pack_bf2(e0, e1);
            pl[kks][hf*2 + 1] = pack_bf2(e2, e3);
        }
        ps0 += __shfl_xor_sync(0xffffffffu, ps0, 1);
        ps0 += __shfl_xor_sync(0xffffffffu, ps0, 2);
        ps1 += __shfl_xor_sync(0xffffffffu, ps1, 1);
        ps1 += __shfl_xor_sync(0xffffffffu, ps1, 2);
        l0 = l0 * corr0 + ps0;
        l1 = l1 * corr1 + ps1;
        m0 = mnew0; m1 = mnew1;
#pragma unroll
        for (int nf = 0; nf < 8; nf++) {
            oacc[nf][0] *= corr0; oacc[nf][1] *= corr0;
            oacc[nf][2] *= corr1; oacc[nf][3] *= corr1;
        }

        // ---- O += P V ----
#pragma unroll
        for (int kks = 0; kks < 4; kks++) {
#pragma unroll
            for (int nf2 = 0; nf2 < 4; nf2++) {
                int r = kks * 16 + (lane & 15);
                int ch = nf2 * 2 + (lane >> 4);
                uint32_t vd = stb + 2*AMAT + r * 128 + ASWZ(r, ch) * 16;
                uint32_t tb[4], vh0[2], vh1[2], vl0[2], vl1[2];
                ldmx4t(tb, vd);
                vh0[0] = tb[0]; vh0[1] = tb[1]; vh1[0] = tb[2]; vh1[1] = tb[3];
                ldmx4t(tb, vd + AMAT);
                vl0[0] = tb[0]; vl0[1] = tb[1]; vl1[0] = tb[2]; vl1[1] = tb[3];
                mma_bf16(oacc[nf2*2],   ph[kks], vh0);
                mma_bf16(oacc[nf2*2],   ph[kks], vl0);
                mma_bf16(oacc[nf2*2],   pl[kks], vh0);
                mma_bf16(oacc[nf2*2+1], ph[kks], vh1);
                mma_bf16(oacc[nf2*2+1], ph[kks], vl1);
                mma_bf16(oacc[nf2*2+1], pl[kks], vh1);
            }
        }
    }

    // ---- epilogue ----
    float inv0 = 1.f / l0, inv1 = 1.f / l1;
    size_t row0 = (size_t)(b*SS + q0 + wid*16 + g);
    size_t row1 = row0 + 8;
#pragma unroll
    for (int nf = 0; nf < 8; nf++) {
        int col = h * DHH + nf * 8 + 2 * qd;
        float v00 = oacc[nf][0] * inv0, v01 = oacc[nf][1] * inv0;
        float v10 = oacc[nf][2] * inv1, v11 = oacc[nf][3] * inv1;
        __nv_bfloat162 hi01 = __floats2bfloat162_rn(v00, v01);
        __nv_bfloat162 lo01 = __floats2bfloat162_rn(v00 - __low2float(hi01), v01 - __high2float(hi01));
        __nv_bfloat162 hi23 = __floats2bfloat162_rn(v10, v11);
        __nv_bfloat162 lo23 = __floats2bfloat162_rn(v10 - __low2float(hi23), v11 - __high2float(hi23));
        *reinterpret_cast<__nv_bfloat162*>(ctx_hi + row0*DD + col) = hi01;
        *reinterpret_cast<__nv_bfloat162*>(ctx_lo + row0*DD + col) = lo01;
        *reinterpret_cast<__nv_bfloat162*>(ctx_hi + row1*DD + col) = hi23;
        *reinterpret_cast<__nv_bfloat162*>(ctx_lo + row1*DD + col) = lo23;
    }
}

// ---------------- launch ----------------------------------------------------
extern "C" void kernel_launch(void* const* d_in, const int* in_sizes, int n_in,
                              void* d_out, int out_size)
{
    (void)in_sizes; (void)n_in; (void)out_size;
    const float* x     = (const float*)d_in[0];
    const float* ln1_s = (const float*)d_in[1];
    const float* ln1_b = (const float*)d_in[2];
    const float* wk    = (const float*)d_in[3];
    const float* wq    = (const float*)d_in[4];
    const float* wv    = (const float*)d_in[5];
    const float* wo    = (const float*)d_in[6];
    const float* ln2_s = (const float*)d_in[7];
    const float* ln2_b = (const float*)d_in[8];
    const float* w1    = (const float*)d_in[9];
    const float* b1    = (const float*)d_in[10];
    const float* w2    = (const float*)d_in[11];
    const float* b2    = (const float*)d_in[12];
    float* out = (float*)d_out;

    static int configured = 0;
    if (!configured) {
        cudaFuncSetAttribute(gemm_hmma, cudaFuncAttributeMaxDynamicSharedMemorySize, HSMEM);
        cudaFuncSetAttribute(gemm_qkv,  cudaFuncAttributeMaxDynamicSharedMemorySize, HSMEM);
        cudaFuncSetAttribute(flash_attn_hmma, cudaFuncAttributeMaxDynamicSharedMemorySize, ASMEM);
        configured = 1;
    }

    __nv_bfloat16 *h_hi, *h_lo, *ctx_hi, *ctx_lo, *h2_hi, *h2_lo, *mid_hi, *mid_lo;
    __nv_bfloat16 *qhp, *qlp, *khp, *klp, *vhp, *vlp;
    __nv_bfloat16 *wqkvt_h, *wqkvt_l, *wot_h, *wot_l;
    __nv_bfloat16 *w1t_h, *w1t_l, *w2t_h, *w2t_l;
    float *mlpin, *rope;
    cudaGetSymbolAddress((void**)&h_hi,  g_h_hi);   cudaGetSymbolAddress((void**)&h_lo,  g_h_lo);
    cudaGetSymbolAddress((void**)&qhp,   g_qh);     cudaGetSymbolAddress((void**)&qlp,   g_ql);
    cudaGetSymbolAddress((void**)&khp,   g_kh);     cudaGetSymbolAddress((void**)&klp,   g_kl);
    cudaGetSymbolAddress((void**)&vhp,   g_vh);     cudaGetSymbolAddress((void**)&vlp,   g_vl);
    cudaGetSymbolAddress((void**)&ctx_hi,g_ctx_hi); cudaGetSymbolAddress((void**)&ctx_lo,g_ctx_lo);
    cudaGetSymbolAddress((void**)&mlpin, g_mlpin);
    cudaGetSymbolAddress((void**)&rope,  g_rope);
    cudaGetSymbolAddress((void**)&h2_hi, g_h2_hi);  cudaGetSymbolAddress((void**)&h2_lo, g_h2_lo);
    cudaGetSymbolAddress((void**)&mid_hi,g_mid_hi); cudaGetSymbolAddress((void**)&mid_lo,g_mid_lo);
    cudaGetSymbolAddress((void**)&wqkvt_h, g_wqkvt_h); cudaGetSymbolAddress((void**)&wqkvt_l, g_wqkvt_l);
    cudaGetSymbolAddress((void**)&wot_h, g_wot_h);  cudaGetSymbolAddress((void**)&wot_l, g_wot_l);
    cudaGetSymbolAddress((void**)&w1t_h, g_w1t_h);  cudaGetSymbolAddress((void**)&w1t_l, g_w1t_l);
    cudaGetSymbolAddress((void**)&w2t_h, g_w2t_h);  cudaGetSymbolAddress((void**)&w2t_l, g_w2t_l);

    // rope table (once per call; deterministic)
    rope_tab<<<(SS*32)/256, 256>>>(rope);

    // merged weight transpose+split: one launch for all 6 weights (12288 tiles)
    tconv_all<<<12288, dim3(32, 8)>>>(wq, wk, wv, wo, w1, w2,
                                      wqkvt_h, wqkvt_l, wot_h, wot_l,
                                      w1t_h, w1t_l, w2t_h, w2t_l);

    // 1. LN1 -> bf16 hi/lo
    ln_bf16<<<ROWS, 256>>>(x, ln1_s, ln1_b, h_hi, h_lo);

    // 2. fused QKV projection + RoPE (q scaled by 1/8)
    gemm_qkv<<<dim3(48, ROWS/BMH), 256, HSMEM>>>(h_hi, h_lo, wqkvt_h, wqkvt_l, rope,
                                                 qhp, qlp, khp, klp, vhp, vlp);

    // 3. HMMA flash attention -> ctx bf16 hi/lo
    flash_attn_hmma<<<dim3(SS/AQT, BB*HH), 256, ASMEM>>>(qhp, qlp, khp, klp, vhp, vlp,
                                                         ctx_hi, ctx_lo);

    // 4. WO projection + residual x -> mlpin (fp32)
    gemm_hmma<<<dim3(DD/BNH, ROWS/BMH), 256, HSMEM>>>(ctx_hi, ctx_lo, wot_h, wot_l, mlpin, DD, DD,
                                   nullptr, x, nullptr, nullptr, 1);

    // 5. LN2 -> bf16 hi/lo
    ln_bf16<<<ROWS, 256>>>(mlpin, ln2_s, ln2_b, h2_hi, h2_lo);

    // 6. MLP up: gelu(h2@w1+b1) -> mid bf16 hi/lo
    gemm_hmma<<<dim3(MM/BNH, ROWS/BMH), 256, HSMEM>>>(h2_hi, h2_lo, w1t_h, w1t_l,
                                   nullptr, MM, DD, b1, nullptr, mid_hi, mid_lo, 2);

    // 7. MLP down + bias + residual -> out (fp32)
    gemm_hmma<<<dim3(DD/BNH, ROWS/BMH), 256, HSMEM>>>(mid_hi, mid_lo, w2t_h, w2t_l, out, DD, MM,
                                   b2, mlpin, nullptr, nullptr, 3);
}

// round 16
// speedup vs baseline: 1.2250x; 1.2250x over previous
#include <cuda_runtime.h>
#include <cuda_bf16.h>
#include <cuda_fp16.h>
#include <math.h>
#include <stdint.h>
#include <string.h>

// Problem constants
#define BB 2
#define SS 2048
#define DD 1024
#define HH 16
#define DHH 64
#define MM 4096
#define ROWS (BB*SS)          // 4096
#define EPS 1e-6f

// HMMA GEMM tiling (128x64 tile, fp16 2-term, 3-stage: 3 CTAs/SM)
#define BMH 128
#define BNH 64
#define BKH 32
#define LDSROW 64                 // bytes per smem row (32 fp16, XOR-swizzled)
#define TILEA (128*LDSROW)        // 8192 bytes (A matrix tile, per term)
#define TILEBB (64*LDSROW)        // 4096 bytes (B matrix tile, single term)
#define STAGE_H (2*TILEA + TILEBB)   // Ah, Al, Bh = 20480
#define HSMEM (3*STAGE_H)         // 61440 (3 stages, 3 CTAs/SM)

// Flash attention tiling (3-stage, SW128-swizzled 128B rows, Q-region reuse)
#define AQT 128
#define AKT 64
#define AMAT 8192
#define ASTAGE (4*AMAT)           // 32768
#define ASMEM (3*ASTAGE)          // 98304

#define GSWZ(row, seg) ((seg) ^ (((row) >> 1) & 3))
#define ASWZ(row, seg) ((seg) ^ ((row) & 7))

// ---------------- scratch (static device globals; no allocations) -----------
__device__ __half        g_h_hi[ROWS*DD],  g_h_lo[ROWS*DD];
__device__ __nv_bfloat16 g_qh[ROWS*DD], g_ql[ROWS*DD];
__device__ __nv_bfloat16 g_kh[ROWS*DD], g_kl[ROWS*DD];
__device__ __nv_bfloat16 g_vh[ROWS*DD], g_vl[ROWS*DD];
__device__ __half        g_ctx_hi[ROWS*DD], g_ctx_lo[ROWS*DD];
__device__ float         g_mlpin[ROWS*DD];
__device__ __half        g_h2_hi[ROWS*DD], g_h2_lo[ROWS*DD];
__device__ __half        g_mid_hi[ROWS*MM], g_mid_lo[ROWS*MM];
__device__ float         g_rope[SS*64];
// transposed fp16 weights [N][K] (single term); qkv stacked [3*DD][DD]
__device__ __half        g_wqkvt[3*DD*DD];
__device__ __half        g_wot[DD*DD];
__device__ __half        g_w1t[MM*DD];
__device__ __half        g_w2t[DD*MM];

// ---------------- helpers ----------------------------------------------------
__device__ __forceinline__ uint32_t smem_to_u32(const void* p) {
    uint32_t a;
    asm("{ .reg .u64 t; cvta.to.shared.u64 t, %1; cvt.u32.u64 %0, t; }" : "=r"(a) : "l"(p));
    return a;
}
__device__ __forceinline__ void cp16(uint32_t saddr, const void* gaddr) {
    asm volatile("cp.async.cg.shared.global [%0], [%1], 16;" :: "r"(saddr), "l"(gaddr) : "memory");
}
__device__ __forceinline__ void cp_commit() {
    asm volatile("cp.async.commit_group;" ::: "memory");
}
__device__ __forceinline__ void cp_wait1() {
    asm volatile("cp.async.wait_group 1;" ::: "memory");
}
__device__ __forceinline__ void ldmx4(uint32_t* d, uint32_t addr) {
    asm volatile("ldmatrix.sync.aligned.m8n8.x4.shared.b16 {%0,%1,%2,%3}, [%4];"
                 : "=r"(d[0]), "=r"(d[1]), "=r"(d[2]), "=r"(d[3]) : "r"(addr));
}
__device__ __forceinline__ void ldmx4t(uint32_t* d, uint32_t addr) {
    asm volatile("ldmatrix.sync.aligned.m8n8.x4.trans.shared.b16 {%0,%1,%2,%3}, [%4];"
                 : "=r"(d[0]), "=r"(d[1]), "=r"(d[2]), "=r"(d[3]) : "r"(addr));
}
__device__ __forceinline__ void mma_bf16(float* c, const uint32_t* a, const uint32_t* b) {
    asm volatile("mma.sync.aligned.m16n8k16.row.col.f32.bf16.bf16.f32 "
                 "{%0,%1,%2,%3}, {%4,%5,%6,%7}, {%8,%9}, {%0,%1,%2,%3};"
                 : "+f"(c[0]), "+f"(c[1]), "+f"(c[2]), "+f"(c[3])
                 : "r"(a[0]), "r"(a[1]), "r"(a[2]), "r"(a[3]), "r"(b[0]), "r"(b[1]));
}
__device__ __forceinline__ void mma_fp16(float* c, const uint32_t* a, const uint32_t* b) {
    asm volatile("mma.sync.aligned.m16n8k16.row.col.f32.f16.f16.f32 "
                 "{%0,%1,%2,%3}, {%4,%5,%6,%7}, {%8,%9}, {%0,%1,%2,%3};"
                 : "+f"(c[0]), "+f"(c[1]), "+f"(c[2]), "+f"(c[3])
                 : "r"(a[0]), "r"(a[1]), "r"(a[2]), "r"(a[3]), "r"(b[0]), "r"(b[1]));
}
__device__ __forceinline__ void split_bf16(float v, __nv_bfloat16& h, __nv_bfloat16& l) {
    h = __float2bfloat16(v);
    l = __float2bfloat16(v - __bfloat162float(h));
}
__device__ __forceinline__ void split_fp16(float v, __half& h, __half& l) {
    h = __float2half(v);
    l = __float2half(v - __half2float(h));
}
__device__ __forceinline__ uint32_t pack_bf2(float a, float b) {
    __nv_bfloat162 t = __floats2bfloat162_rn(a, b);
    return *reinterpret_cast<uint32_t*>(&t);
}
// fast tanh-gelu via sigmoid identity
__device__ __forceinline__ float gelu_f(float x) {
    float u2 = 1.5957691216057308f * (x + 0.044715f * x * x * x);
    float e = __expf(u2);
    return x * (1.0f - __fdividef(1.0f, e + 1.0f));
}

// ---------------- RoPE cos/sin table -----------------------------------------
__global__ void rope_tab(float* __restrict__ tab)
{
    int idx = blockIdx.x * 256 + threadIdx.x;
    int s = idx >> 5, i = idx & 31;
    float freq = powf(10000.0f, -((float)(2*i)) / 64.0f);
    float ang = (float)s * freq;
    float sn, cs;
    sincosf(ang, &sn, &cs);
    tab[s*64 + 2*i]     = cs;
    tab[s*64 + 2*i + 1] = sn;
}

// ---------------- LayerNorm -> fp16 hi/lo (vectorized) ------------------------
__global__ void ln_fp16(const float* __restrict__ x,
                        const float* __restrict__ gamma,
                        const float* __restrict__ beta,
                        __half* __restrict__ oh,
                        __half* __restrict__ ol)
{
    __shared__ float red0[8], red1[8];
    int row = blockIdx.x;
    int t = threadIdx.x;
    const float* xr = x + (size_t)row * DD;
    float4 xv = *(const float4*)(xr + 4*t);
    float sum = xv.x + xv.y + xv.z + xv.w;
    float sq  = xv.x*xv.x + xv.y*xv.y + xv.z*xv.z + xv.w*xv.w;
#pragma unroll
    for (int o = 16; o; o >>= 1) {
        sum += __shfl_xor_sync(0xffffffffu, sum, o);
        sq  += __shfl_xor_sync(0xffffffffu, sq,  o);
    }
    if ((t & 31) == 0) { red0[t >> 5] = sum; red1[t >> 5] = sq; }
    __syncthreads();
    if (t < 32) {
        float s = (t < 8) ? red0[t] : 0.f;
        float q = (t < 8) ? red1[t] : 0.f;
#pragma unroll
        for (int o = 4; o; o >>= 1) {
            s += __shfl_xor_sync(0xffffffffu, s, o);
            q += __shfl_xor_sync(0xffffffffu, q, o);
        }
        if (t == 0) { red0[0] = s; red1[0] = q; }
    }
    __syncthreads();
    float mean = red0[0] * (1.f / (float)DD);
    float var  = red1[0] * (1.f / (float)DD) - mean*mean;
    float rstd = rsqrtf(var + EPS);
    float4 gv = *(const float4*)(gamma + 4*t);
    float4 bv = *(const float4*)(beta + 4*t);
    float v0 = (xv.x - mean) * rstd * gv.x + bv.x;
    float v1 = (xv.y - mean) * rstd * gv.y + bv.y;
    float v2 = (xv.z - mean) * rstd * gv.z + bv.z;
    float v3 = (xv.w - mean) * rstd * gv.w + bv.w;
    __half2 h01 = __floats2half2_rn(v0, v1);
    __half2 h23 = __floats2half2_rn(v2, v3);
    __half2 l01 = __floats2half2_rn(v0 - __half2float(__low2half(h01)),
                                    v1 - __half2float(__high2half(h01)));
    __half2 l23 = __floats2half2_rn(v2 - __half2float(__low2half(h23)),
                                    v3 - __half2float(__high2half(h23)));
    size_t base = (size_t)row * DD + 4*t;
    uint2 hp = make_uint2(*reinterpret_cast<uint32_t*>(&h01), *reinterpret_cast<uint32_t*>(&h23));
    uint2 lp = make_uint2(*reinterpret_cast<uint32_t*>(&l01), *reinterpret_cast<uint32_t*>(&l23));
    *reinterpret_cast<uint2*>(oh + base) = hp;
    *reinterpret_cast<uint2*>(ol + base) = lp;
}

// ---------------- merged weight transpose -> fp16 (all 6 weights) ------------
__global__ void tconv_all(const float* __restrict__ wq, const float* __restrict__ wk,
                          const float* __restrict__ wv, const float* __restrict__ wo,
                          const float* __restrict__ w1, const float* __restrict__ w2,
                          __half* __restrict__ wqkvt, __half* __restrict__ wot,
                          __half* __restrict__ w1t,   __half* __restrict__ w2t)
{
    __shared__ float t[32][33];
    int bid = blockIdx.x;
    const float* W; __half* Th;
    int K, N, tile;
    if (bid < 4096) {
        int w = bid >> 10; tile = bid & 1023;
        K = DD; N = DD;
        if (w == 0)      { W = wq; Th = wqkvt; }
        else if (w == 1) { W = wk; Th = wqkvt + DD*DD; }
        else if (w == 2) { W = wv; Th = wqkvt + 2*DD*DD; }
        else             { W = wo; Th = wot; }
    } else if (bid < 8192) {
        tile = bid - 4096; K = DD; N = MM;
        W = w1; Th = w1t;
    } else {
        tile = bid - 8192; K = MM; N = DD;
        W = w2; Th = w2t;
    }
    int ntx = N >> 5;
    int n0 = (tile % ntx) * 32, k0 = (tile / ntx) * 32;
    int tx = threadIdx.x, ty = threadIdx.y;
#pragma unroll
    for (int j = 0; j < 32; j += 8)
        t[ty + j][tx] = W[(size_t)(k0 + ty + j) * N + n0 + tx];
    __syncthreads();
#pragma unroll
    for (int j = 0; j < 32; j += 8) {
        float v = t[tx][ty + j];
        size_t o = (size_t)(n0 + ty + j) * K + k0 + tx;
        Th[o] = __float2half(v);
    }
}

// ---------------- shared GEMM machinery (fp16 2-term, 3-stage) ----------------
struct GemmAcc { float a[2][4][4]; };

__device__ __forceinline__ void gemm_mainloop(
    uint32_t sb, int tid, int wid, int lane,
    const __half* Ahb, const __half* Alb, const __half* Bhb,
    int Kdim, GemmAcc& acc)
{
    int nch = Kdim / BKH;
    int wm = (wid & 3) * 32;
    int wn = (wid >> 2) * 32;

    auto load_chunk = [&](int c, int s) {
        int k0 = c * BKH;
        uint32_t st = sb + s * STAGE_H;
#pragma unroll
        for (int i = tid; i < 512; i += 256) {
            int row = i >> 2, seg = i & 3;
            uint32_t so = st + row * LDSROW + GSWZ(row, seg) * 16;
            size_t go = (size_t)row * Kdim + k0 + seg * 8;
            cp16(so,           Ahb + go);
            cp16(so + TILEA,   Alb + go);
            if (i < 256) {
                uint32_t sob = st + 2*TILEA + row * LDSROW + GSWZ(row, seg) * 16;
                cp16(sob, Bhb + go);
            }
        }
    };

    load_chunk(0, 0);
    cp_commit();
    load_chunk(1, 1);
    cp_commit();

    for (int c = 0; c < nch; c++) {
        int s = c % 3;
        cp_wait1();
        __syncthreads();
        if (c + 2 < nch) load_chunk(c + 2, (c + 2) % 3);
        cp_commit();

        uint32_t st = sb + s * STAGE_H;
#pragma unroll
        for (int ks = 0; ks < 2; ks++) {
            int colb = ks * 16 + (lane >> 4) * 8;
            uint32_t ah[2][4], al[2][4];
#pragma unroll
            for (int mf = 0; mf < 2; mf++) {
                int r = wm + mf * 16 + (lane & 15);
                uint32_t ad = st + r * LDSROW + GSWZ(r, colb >> 3) * 16;
                ldmx4(ah[mf], ad);
                ldmx4(al[mf], ad + TILEA);
            }
#pragma unroll
            for (int nf2 = 0; nf2 < 2; nf2++) {
                int r = wn + nf2 * 16 + ((lane >> 3) & 1) * 8 + (lane & 7);
                uint32_t bd = st + 2*TILEA + r * LDSROW + GSWZ(r, colb >> 3) * 16;
                uint32_t tb[4], bh0[2], bh1[2];
                ldmx4(tb, bd);
                bh0[0] = tb[0]; bh0[1] = tb[2]; bh1[0] = tb[1]; bh1[1] = tb[3];
#pragma unroll
                for (int mf = 0; mf < 2; mf++) {
                    mma_fp16(acc.a[mf][nf2*2],   ah[mf], bh0);
                    mma_fp16(acc.a[mf][nf2*2],   al[mf], bh0);
                    mma_fp16(acc.a[mf][nf2*2+1], ah[mf], bh1);
                    mma_fp16(acc.a[mf][nf2*2+1], al[mf], bh1);
                }
            }
        }
    }
}

// ---------------- generic GEMM kernel ----------------------------------------
// modes: 1 C=acc+resid; 2 Oh/Ol=split_fp16(gelu(acc+bias)); 3 C=acc+bias+resid
__global__ __launch_bounds__(256, 3)
void gemm_hmma(const __half* __restrict__ Ah, const __half* __restrict__ Al,
               const __half* __restrict__ Bh,
               float* __restrict__ C, int Ndim, int Kdim,
               const float* __restrict__ bias, const float* __restrict__ resid,
               __half* __restrict__ Oh, __half* __restrict__ Ol,
               int mode)
{
    extern __shared__ char hs[];
    uint32_t sb = smem_to_u32(hs);
    int tid = threadIdx.x, wid = tid >> 5, lane = tid & 31;
    int bx = blockIdx.x, by = blockIdx.y;

    GemmAcc acc;
#pragma unroll
    for (int i = 0; i < 2; i++)
#pragma unroll
        for (int j = 0; j < 4; j++)
#pragma unroll
            for (int r = 0; r < 4; r++) acc.a[i][j][r] = 0.f;

    gemm_mainloop(sb, tid, wid, lane,
                  Ah + (size_t)by * BMH * Kdim, Al + (size_t)by * BMH * Kdim,
                  Bh + (size_t)bx * BNH * Kdim, Kdim, acc);

    int wm = (wid & 3) * 32, wn = (wid >> 2) * 32;
    int g = lane >> 2, qd = lane & 3;
#pragma unroll
    for (int mf = 0; mf < 2; mf++) {
#pragma unroll
        for (int half = 0; half < 2; half++) {
            int grow = by * BMH + wm + mf * 16 + g + half * 8;
#pragma unroll
            for (int nf = 0; nf < 4; nf++) {
                int gcol = bx * BNH + wn + nf * 8 + qd * 2;
                float v0 = acc.a[mf][nf][half*2 + 0];
                float v1 = acc.a[mf][nf][half*2 + 1];
                size_t o = (size_t)grow * Ndim + gcol;
                if (mode == 1) {
                    C[o] = v0 + resid[o]; C[o+1] = v1 + resid[o+1];
                } else if (mode == 2) {
                    float g0 = gelu_f(v0 + bias[gcol]);
                    float g1 = gelu_f(v1 + bias[gcol+1]);
                    __half hh, ll;
                    split_fp16(g0, hh, ll); Oh[o] = hh; Ol[o] = ll;
                    split_fp16(g1, hh, ll); Oh[o+1] = hh; Ol[o+1] = ll;
                } else {
                    C[o]   = v0 + bias[gcol]   + resid[o];
                    C[o+1] = v1 + bias[gcol+1] + resid[o+1];
                }
            }
        }
    }
}

// ---------------- fused QKV GEMM with in-register RoPE -----------------------
// W: stacked [3*DD][DD] fp16. bx in [0,48): mat = bx>>4, bn = bx&15.
// Emits q/k/v as bf16 hi/lo for the bf16x3 attention kernel.
__global__ __launch_bounds__(256, 3)
void gemm_qkv(const __half* __restrict__ Ah, const __half* __restrict__ Al,
              const __half* __restrict__ Wh,
              const float* __restrict__ rope,
              __nv_bfloat16* __restrict__ qh, __nv_bfloat16* __restrict__ ql,
              __nv_bfloat16* __restrict__ kh, __nv_bfloat16* __restrict__ kl,
              __nv_bfloat16* __restrict__ vh, __nv_bfloat16* __restrict__ vl)
{
    extern __shared__ char hs[];
    uint32_t sb = smem_to_u32(hs);
    int tid = threadIdx.x, wid = tid >> 5, lane = tid & 31;
    int bx = blockIdx.x, by = blockIdx.y;
    int mat = bx >> 4, bn = bx & 15;

    GemmAcc acc;
#pragma unroll
    for (int i = 0; i < 2; i++)
#pragma unroll
        for (int j = 0; j < 4; j++)
#pragma unroll
            for (int r = 0; r < 4; r++) acc.a[i][j][r] = 0.f;

    size_t woff = ((size_t)mat * DD + (size_t)bn * BNH) * DD;
    gemm_mainloop(sb, tid, wid, lane,
                  Ah + (size_t)by * BMH * DD, Al + (size_t)by * BMH * DD,
                  Wh + woff, DD, acc);

    __nv_bfloat16* Oh = (mat == 0) ? qh : (mat == 1) ? kh : vh;
    __nv_bfloat16* Ol = (mat == 0) ? ql : (mat == 1) ? kl : vl;
    float qscale = (mat == 0) ? 0.125f : 1.0f;

    int wm = (wid & 3) * 32, wn = (wid >> 2) * 32;
    int g = lane >> 2, qd = lane & 3;
#pragma unroll
    for (int mf = 0; mf < 2; mf++) {
#pragma unroll
        for (int half = 0; half < 2; half++) {
            int grow = by * BMH + wm + mf * 16 + g + half * 8;
            int srow = grow & (SS - 1);
#pragma unroll
            for (int nf = 0; nf < 4; nf++) {
                int gcol = bn * BNH + wn + nf * 8 + qd * 2;
                float v0 = acc.a[mf][nf][half*2 + 0];
                float v1 = acc.a[mf][nf][half*2 + 1];
                size_t o = (size_t)grow * DD + gcol;
                if (mat < 2) {
                    int i2 = gcol & 63;
                    float2 cs = *(const float2*)(rope + (size_t)srow * 64 + i2);
                    float r0 = (v0 * cs.x - v1 * cs.y) * qscale;
                    float r1 = (v0 * cs.y + v1 * cs.x) * qscale;
                    __nv_bfloat16 hh, ll;
                    split_bf16(r0, hh, ll); Oh[o] = hh; Ol[o] = ll;
                    split_bf16(r1, hh, ll); Oh[o+1] = hh; Ol[o+1] = ll;
                } else {
                    __nv_bfloat16 hh, ll;
                    split_bf16(v0, hh, ll); Oh[o] = hh; Ol[o] = ll;
                    split_bf16(v1, hh, ll); Oh[o+1] = hh; Ol[o+1] = ll;
                }
            }
        }
    }
}

// ---------------- HMMA flash attention (bf16x3, 3-stage, Q-region reuse) -----
// Emits ctx as fp16 hi/lo for the fp16 WO GEMM.
__global__ __launch_bounds__(256, 2)
void flash_attn_hmma(const __nv_bfloat16* __restrict__ qh, const __nv_bfloat16* __restrict__ ql,
                     const __nv_bfloat16* __restrict__ kh, const __nv_bfloat16* __restrict__ kl,
                     const __nv_bfloat16* __restrict__ vh, const __nv_bfloat16* __restrict__ vl,
                     __half* __restrict__ ctx_hi, __half* __restrict__ ctx_lo)
{
    extern __shared__ char fs[];
    uint32_t sb = smem_to_u32(fs);
    int tid = threadIdx.x, wid = tid >> 5, lane = tid & 31;
    int g = lane >> 2, qd = lane & 3;
    int qt = blockIdx.x, bh = blockIdx.y;
    int b = bh >> 4, h = bh & 15;
    int q0 = qt * AQT;

    const __nv_bfloat16* qhb = qh + ((size_t)(b*SS + q0)) * DD + h * DHH;
    const __nv_bfloat16* qlb = ql + ((size_t)(b*SS + q0)) * DD + h * DHH;
    const __nv_bfloat16* khb = kh + ((size_t)(b*SS)) * DD + h * DHH;
    const __nv_bfloat16* klb = kl + ((size_t)(b*SS)) * DD + h * DHH;
    const __nv_bfloat16* vhb = vh + ((size_t)(b*SS)) * DD + h * DHH;
    const __nv_bfloat16* vlb = vl + ((size_t)(b*SS)) * DD + h * DHH;

    auto load_tile = [&](int t) {
        uint32_t st = sb + ((t % 3 == 0) ? 32768u : (t % 3 == 1) ? 65536u : 0u);
        const __nv_bfloat16* srcs[4] = {khb, klb, vhb, vlb};
#pragma unroll
        for (int i = tid; i < 2048; i += 256) {
            int mtx = i >> 9;
            int j = i & 511;
            int row = j >> 3, seg = j & 7;
            uint32_t so = st + mtx * AMAT + row * 128 + ASWZ(row, seg) * 16;
            cp16(so, srcs[mtx] + (size_t)(t*AKT + row) * DD + seg * 8);
        }
    };

#pragma unroll
    for (int i = tid; i < 2048; i += 256) {
        int mtx = i >> 10;
        int j = i & 1023;
        int row = j >> 3, seg = j & 7;
        uint32_t so = sb + mtx * 16384 + row * 128 + ASWZ(row, seg) * 16;
        const __nv_bfloat16* src = (mtx ? qlb : qhb) + (size_t)row * DD + seg * 8;
        cp16(so, src);
    }
    load_tile(0);
    cp_commit();
    load_tile(1);
    cp_commit();

    float oacc[8][4];
#pragma unroll
    for (int i = 0; i < 8; i++)
#pragma unroll
        for (int j = 0; j < 4; j++) oacc[i][j] = 0.f;
    float m0 = -INFINITY, m1 = -INFINITY, l0 = 0.f, l1 = 0.f;
    uint32_t qfh[4][4], qfl[4][4];

    int ntiles = SS / AKT;   // 32
    for (int t = 0; t < ntiles; t++) {
        uint32_t stb = sb + ((t % 3 == 0) ? 32768u : (t % 3 == 1) ? 65536u : 0u);
        cp_wait1();
        __syncthreads();

        if (t == 0) {
#pragma unroll
            for (int ks = 0; ks < 4; ks++) {
                int r = wid * 16 + (lane & 15);
                int ch = ks * 2 + (lane >> 4);
                uint32_t ad = sb + r * 128 + ASWZ(r, ch) * 16;
                ldmx4(qfh[ks], ad);
                ldmx4(qfl[ks], ad + 16384);
            }
            __syncthreads();
        }

        if (t + 2 < ntiles) load_tile(t + 2);
        cp_commit();

        // ---- S = Q K^T ----
        float sacc[8][4];
#pragma unroll
        for (int i = 0; i < 8; i++)
#pragma unroll
            for (int j = 0; j < 4; j++) sacc[i][j] = 0.f;
#pragma unroll
        for (int ks = 0; ks < 4; ks++) {
#pragma unroll
            for (int nf2 = 0; nf2 < 4; nf2++) {
                int r = nf2 * 16 + ((lane >> 3) & 1) * 8 + (lane & 7);
                int ch = ks * 2 + (lane >> 4);
                uint32_t ad = stb + r * 128 + ASWZ(r, ch) * 16;
                uint32_t tb[4], kh0[2], kh1[2], kl0[2], kl1[2];
                ldmx4(tb, ad);
                kh0[0] = tb[0]; kh0[1] = tb[2]; kh1[0] = tb[1]; kh1[1] = tb[3];
                ldmx4(tb, ad + AMAT);
                kl0[0] = tb[0]; kl0[1] = tb[2]; kl1[0] = tb[1]; kl1[1] = tb[3];
                mma_bf16(sacc[nf2*2],   qfh[ks], kh0);
                mma_bf16(sacc[nf2*2],   qfh[ks], kl0);
                mma_bf16(sacc[nf2*2],   qfl[ks], kh0);
                mma_bf16(sacc[nf2*2+1], qfh[ks], kh1);
                mma_bf16(sacc[nf2*2+1], qfh[ks], kl1);
                mma_bf16(sacc[nf2*2+1], qfl[ks], kh1);
            }
        }

        // ---- online softmax on fragments ----
        float mx0 = -INFINITY, mx1 = -INFINITY;
#pragma unroll
        for (int nf = 0; nf < 8; nf++) {
            mx0 = fmaxf(mx0, fmaxf(sacc[nf][0], sacc[nf][1]));
            mx1 = fmaxf(mx1, fmaxf(sacc[nf][2], sacc[nf][3]));
        }
        mx0 = fmaxf(mx0, __shfl_xor_sync(0xffffffffu, mx0, 1));
        mx0 = fmaxf(mx0, __shfl_xor_sync(0xffffffffu, mx0, 2));
        mx1 = fmaxf(mx1, __shfl_xor_sync(0xffffffffu, mx1, 1));
        mx1 = fmaxf(mx1, __shfl_xor_sync(0xffffffffu, mx1, 2));
        float mnew0 = fmaxf(m0, mx0), mnew1 = fmaxf(m1, mx1);
        float corr0 = __expf(m0 - mnew0), corr1 = __expf(m1 - mnew1);

        uint32_t ph[4][4], pl[4][4];
        float ps0 = 0.f, ps1 = 0.f;
#pragma unroll
        for (int nf = 0; nf < 8; nf++) {
            float p0 = __expf(sacc[nf][0] - mnew0);
            float p1 = __expf(sacc[nf][1] - mnew0);
            float p2 = __expf(sacc[nf][2] - mnew1);
            float p3 = __expf(sacc[nf][3] - mnew1);
            ps0 += p0 + p1; ps1 += p2 + p3;
            __nv_bfloat162 h01 = __floats2bfloat162_rn(p0, p1);
            __nv_bfloat162 h23 = __floats2bfloat162_rn(p2, p3);
            float e0 = p0 - __low2float(h01), e1 = p1 - __high2float(h01);
            float e2 = p2 - __low2float(h23), e3 = p3 - __high2float(h23);
            int kks = nf >> 1, hf = nf & 1;
            ph[kks][hf*2 + 0] = *reinterpret_cast<uint32_t*>(&h01);
            ph[kks][hf*2 + 1] = *reinterpret_cast<uint32_t*>(&h23);
            pl[kks][hf*2 + 0] = pack_bf2(e0, e1);
            pl[kks][hf*2 + 1] = pack_bf2(e2, e3);
        }
        ps0 += __shfl_xor_sync(0xffffffffu, ps0, 1);
        ps0 += __shfl_xor_sync(0xffffffffu, ps0, 2);
        ps1 += __shfl_xor_sync(0xffffffffu, ps1, 1);
        ps1 += __shfl_xor_sync(0xffffffffu, ps1, 2);
        l0 = l0 * corr0 + ps0;
        l1 = l1 * corr1 + ps1;
        m0 = mnew0; m1 = mnew1;
#pragma unroll
        for (int nf = 0; nf < 8; nf++) {
            oacc[nf][0] *= corr0; oacc[nf][1] *= corr0;
            oacc[nf][2] *= corr1; oacc[nf][3] *= corr1;
        }

        // ---- O += P V ----
#pragma unroll
        for (int kks = 0; kks < 4; kks++) {
#pragma unroll
            for (int nf2 = 0; nf2 < 4; nf2++) {
                int r = kks * 16 + (lane & 15);
                int ch = nf2 * 2 + (lane >> 4);
                uint32_t vd = stb + 2*AMAT + r * 128 + ASWZ(r, ch) * 16;
                uint32_t tb[4], vh0[2], vh1[2], vl0[2], vl1[2];
                ldmx4t(tb, vd);
                vh0[0] = tb[0]; vh0[1] = tb[1]; vh1[0] = tb[2]; vh1[1] = tb[3];
                ldmx4t(tb, vd + AMAT);
                vl0[0] = tb[0]; vl0[1] = tb[1]; vl1[0] = tb[2]; vl1[1] = tb[3];
                mma_bf16(oacc[nf2*2],   ph[kks], vh0);
                mma_bf16(oacc[nf2*2],   ph[kks], vl0);
                mma_bf16(oacc[nf2*2],   pl[kks], vh0);
                mma_bf16(oacc[nf2*2+1], ph[kks], vh1);
                mma_bf16(oacc[nf2*2+1], ph[kks], vl1);
                mma_bf16(oacc[nf2*2+1], pl[kks], vh1);
            }
        }
    }

    // ---- epilogue: fp16 hi/lo ----
    float inv0 = 1.f / l0, inv1 = 1.f / l1;
    size_t row0 = (size_t)(b*SS + q0 + wid*16 + g);
    size_t row1 = row0 + 8;
#pragma unroll
    for (int nf = 0; nf < 8; nf++) {
        int col = h * DHH + nf * 8 + 2 * qd;
        float v00 = oacc[nf][0] * inv0, v01 = oacc[nf][1] * inv0;
        float v10 = oacc[nf][2] * inv1, v11 = oacc[nf][3] * inv1;
        __half2 hi01 = __floats2half2_rn(v00, v01);
        __half2 lo01 = __floats2half2_rn(v00 - __half2float(__low2half(hi01)),
                                         v01 - __half2float(__high2half(hi01)));
        __half2 hi23 = __floats2half2_rn(v10, v11);
        __half2 lo23 = __floats2half2_rn(v10 - __half2float(__low2half(hi23)),
                                         v11 - __half2float(__high2half(hi23)));
        *reinterpret_cast<__half2*>(ctx_hi + row0*DD + col) = hi01;
        *reinterpret_cast<__half2*>(ctx_lo + row0*DD + col) = lo01;
        *reinterpret_cast<__half2*>(ctx_hi + row1*DD + col) = hi23;
        *reinterpret_cast<__half2*>(ctx_lo + row1*DD + col) = lo23;
    }
}

// ---------------- launch ----------------------------------------------------
extern "C" void kernel_launch(void* const* d_in, const int* in_sizes, int n_in,
                              void* d_out, int out_size)
{
    (void)in_sizes; (void)n_in; (void)out_size;
    const float* x     = (const float*)d_in[0];
    const float* ln1_s = (const float*)d_in[1];
    const float* ln1_b = (const float*)d_in[2];
    const float* wk    = (const float*)d_in[3];
    const float* wq    = (const float*)d_in[4];
    const float* wv    = (const float*)d_in[5];
    const float* wo    = (const float*)d_in[6];
    const float* ln2_s = (const float*)d_in[7];
    const float* ln2_b = (const float*)d_in[8];
    const float* w1    = (const float*)d_in[9];
    const float* b1    = (const float*)d_in[10];
    const float* w2    = (const float*)d_in[11];
    const float* b2    = (const float*)d_in[12];
    float* out = (float*)d_out;

    static int configured = 0;
    if (!configured) {
        cudaFuncSetAttribute(gemm_hmma, cudaFuncAttributeMaxDynamicSharedMemorySize, HSMEM);
        cudaFuncSetAttribute(gemm_qkv,  cudaFuncAttributeMaxDynamicSharedMemorySize, HSMEM);
        cudaFuncSetAttribute(flash_attn_hmma, cudaFuncAttributeMaxDynamicSharedMemorySize, ASMEM);
        configured = 1;
    }

    __half *h_hi, *h_lo, *ctx_hi, *ctx_lo, *h2_hi, *h2_lo, *mid_hi, *mid_lo;
    __nv_bfloat16 *qhp, *qlp, *khp, *klp, *vhp, *vlp;
    __half *wqkvt, *wot, *w1t, *w2t;
    float *mlpin, *rope;
    cudaGetSymbolAddress((void**)&h_hi,  g_h_hi);   cudaGetSymbolAddress((void**)&h_lo,  g_h_lo);
    cudaGetSymbolAddress((void**)&qhp,   g_qh);     cudaGetSymbolAddress((void**)&qlp,   g_ql);
    cudaGetSymbolAddress((void**)&khp,   g_kh);     cudaGetSymbolAddress((void**)&klp,   g_kl);
    cudaGetSymbolAddress((void**)&vhp,   g_vh);     cudaGetSymbolAddress((void**)&vlp,   g_vl);
    cudaGetSymbolAddress((void**)&ctx_hi,g_ctx_hi); cudaGetSymbolAddress((void**)&ctx_lo,g_ctx_lo);
    cudaGetSymbolAddress((void**)&mlpin, g_mlpin);
    cudaGetSymbolAddress((void**)&rope,  g_rope);
    cudaGetSymbolAddress((void**)&h2_hi, g_h2_hi);  cudaGetSymbolAddress((void**)&h2_lo, g_h2_lo);
    cudaGetSymbolAddress((void**)&mid_hi,g_mid_hi); cudaGetSymbolAddress((void**)&mid_lo,g_mid_lo);
    cudaGetSymbolAddress((void**)&wqkvt, g_wqkvt);
    cudaGetSymbolAddress((void**)&wot,   g_wot);
    cudaGetSymbolAddress((void**)&w1t,   g_w1t);
    cudaGetSymbolAddress((void**)&w2t,   g_w2t);

    rope_tab<<<(SS*32)/256, 256>>>(rope);
    tconv_all<<<12288, dim3(32, 8)>>>(wq, wk, wv, wo, w1, w2, wqkvt, wot, w1t, w2t);

    // 1. LN1 -> fp16 hi/lo
    ln_fp16<<<ROWS, 256>>>(x, ln1_s, ln1_b, h_hi, h_lo);

    // 2. fused QKV projection + RoPE (emits bf16 hi/lo for attention)
    gemm_qkv<<<dim3(48, ROWS/BMH), 256, HSMEM>>>(h_hi, h_lo, wqkvt, rope,
                                                 qhp, qlp, khp, klp, vhp, vlp);

    // 3. HMMA flash attention (bf16x3) -> ctx fp16 hi/lo
    flash_attn_hmma<<<dim3(SS/AQT, BB*HH), 256, ASMEM>>>(qhp, qlp, khp, klp, vhp, vlp,
                                                         ctx_hi, ctx_lo);

    // 4. WO projection + residual x -> mlpin (fp32)
    gemm_hmma<<<dim3(DD/BNH, ROWS/BMH), 256, HSMEM>>>(ctx_hi, ctx_lo, wot, mlpin, DD, DD,
                                   nullptr, x, nullptr, nullptr, 1);

    // 5. LN2 -> fp16 hi/lo
    ln_fp16<<<ROWS, 256>>>(mlpin, ln2_s, ln2_b, h2_hi, h2_lo);

    // 6. MLP up: gelu(h2@w1+b1) -> mid fp16 hi/lo
    gemm_hmma<<<dim3(MM/BNH, ROWS/BMH), 256, HSMEM>>>(h2_hi, h2_lo, w1t,
                                   nullptr, MM, DD, b1, nullptr, mid_hi, mid_lo, 2);

    // 7. MLP down + bias + residual -> out (fp32)
    gemm_hmma<<<dim3(DD/BNH, ROWS/BMH), 256, HSMEM>>>(mid_hi, mid_lo, w2t, out, DD, MM,
                                   b2, mlpin, nullptr, nullptr, 3);
}

// round 17
// speedup vs baseline: 1.3572x; 1.1080x over previous
#include <cuda_runtime.h>
#include <cuda_bf16.h>
#include <cuda_fp16.h>
#include <math.h>
#include <stdint.h>
#include <string.h>

// Problem constants
#define BB 2
#define SS 2048
#define DD 1024
#define HH 16
#define DHH 64
#define MM 4096
#define ROWS (BB*SS)          // 4096
#define EPS 1e-6f

// HMMA GEMM tiling (128x64 tile, fp16 2-term, 3-stage: 3 CTAs/SM)
#define BMH 128
#define BNH 64
#define BKH 32
#define LDSROW 64                 // bytes per smem row (32 fp16, XOR-swizzled)
#define TILEA (128*LDSROW)        // 8192 bytes (A matrix tile, per term)
#define TILEBB (64*LDSROW)        // 4096 bytes (B matrix tile, single term)
#define STAGE_H (2*TILEA + TILEBB)   // Ah, Al, Bh = 20480
#define HSMEM (3*STAGE_H)         // 61440 (3 stages, 3 CTAs/SM)

// Flash attention (fp16: Q 2-term, K 1-term, P 1-term, V 2-term; 3-stage ring)
#define AQT 128
#define AKT 64
#define AMAT 8192                 // one matrix tile: 64 rows * 128B
#define ASTAGE (3*AMAT)           // Kh, Vh, Vl = 24576
#define AST1 32768                // stage offset for t%3==0
#define AST2 57344                // stage offset for t%3==1 (stage 2 reuses Q region @0)
#define ASMEM 81920

#define GSWZ(row, seg) ((seg) ^ (((row) >> 1) & 3))
#define ASWZ(row, seg) ((seg) ^ ((row) & 7))

// ---------------- scratch (static device globals; no allocations) -----------
__device__ __half        g_h_hi[ROWS*DD],  g_h_lo[ROWS*DD];
__device__ __half        g_qh[ROWS*DD], g_ql[ROWS*DD];
__device__ __half        g_kh[ROWS*DD];
__device__ __half        g_vh[ROWS*DD], g_vl[ROWS*DD];
__device__ __half        g_ctx_hi[ROWS*DD], g_ctx_lo[ROWS*DD];
__device__ float         g_mlpin[ROWS*DD];
__device__ __half        g_h2_hi[ROWS*DD], g_h2_lo[ROWS*DD];
__device__ __half        g_mid_hi[ROWS*MM], g_mid_lo[ROWS*MM];
__device__ float         g_rope[SS*64];
// transposed fp16 weights [N][K] (single term); qkv stacked [3*DD][DD]
__device__ __half        g_wqkvt[3*DD*DD];
__device__ __half        g_wot[DD*DD];
__device__ __half        g_w1t[MM*DD];
__device__ __half        g_w2t[DD*MM];

// ---------------- helpers ----------------------------------------------------
__device__ __forceinline__ uint32_t smem_to_u32(const void* p) {
    uint32_t a;
    asm("{ .reg .u64 t; cvta.to.shared.u64 t, %1; cvt.u32.u64 %0, t; }" : "=r"(a) : "l"(p));
    return a;
}
__device__ __forceinline__ void cp16(uint32_t saddr, const void* gaddr) {
    asm volatile("cp.async.cg.shared.global [%0], [%1], 16;" :: "r"(saddr), "l"(gaddr) : "memory");
}
__device__ __forceinline__ void cp_commit() {
    asm volatile("cp.async.commit_group;" ::: "memory");
}
__device__ __forceinline__ void cp_wait1() {
    asm volatile("cp.async.wait_group 1;" ::: "memory");
}
__device__ __forceinline__ void ldmx4(uint32_t* d, uint32_t addr) {
    asm volatile("ldmatrix.sync.aligned.m8n8.x4.shared.b16 {%0,%1,%2,%3}, [%4];"
                 : "=r"(d[0]), "=r"(d[1]), "=r"(d[2]), "=r"(d[3]) : "r"(addr));
}
__device__ __forceinline__ void ldmx4t(uint32_t* d, uint32_t addr) {
    asm volatile("ldmatrix.sync.aligned.m8n8.x4.trans.shared.b16 {%0,%1,%2,%3}, [%4];"
                 : "=r"(d[0]), "=r"(d[1]), "=r"(d[2]), "=r"(d[3]) : "r"(addr));
}
__device__ __forceinline__ void mma_fp16(float* c, const uint32_t* a, const uint32_t* b) {
    asm volatile("mma.sync.aligned.m16n8k16.row.col.f32.f16.f16.f32 "
                 "{%0,%1,%2,%3}, {%4,%5,%6,%7}, {%8,%9}, {%0,%1,%2,%3};"
                 : "+f"(c[0]), "+f"(c[1]), "+f"(c[2]), "+f"(c[3])
                 : "r"(a[0]), "r"(a[1]), "r"(a[2]), "r"(a[3]), "r"(b[0]), "r"(b[1]));
}
__device__ __forceinline__ void split_fp16(float v, __half& h, __half& l) {
    h = __float2half(v);
    l = __float2half(v - __half2float(h));
}
__device__ __forceinline__ uint32_t pack_h2(float a, float b) {
    __half2 t = __floats2half2_rn(a, b);
    return *reinterpret_cast<uint32_t*>(&t);
}
// fast tanh-gelu via sigmoid identity
__device__ __forceinline__ float gelu_f(float x) {
    float u2 = 1.5957691216057308f * (x + 0.044715f * x * x * x);
    float e = __expf(u2);
    return x * (1.0f - __fdividef(1.0f, e + 1.0f));
}

// ---------------- RoPE cos/sin table -----------------------------------------
__global__ void rope_tab(float* __restrict__ tab)
{
    int idx = blockIdx.x * 256 + threadIdx.x;
    int s = idx >> 5, i = idx & 31;
    float freq = powf(10000.0f, -((float)(2*i)) / 64.0f);
    float ang = (float)s * freq;
    float sn, cs;
    sincosf(ang, &sn, &cs);
    tab[s*64 + 2*i]     = cs;
    tab[s*64 + 2*i + 1] = sn;
}

// ---------------- LayerNorm -> fp16 hi/lo (vectorized) ------------------------
__global__ void ln_fp16(const float* __restrict__ x,
                        const float* __restrict__ gamma,
                        const float* __restrict__ beta,
                        __half* __restrict__ oh,
                        __half* __restrict__ ol)
{
    __shared__ float red0[8], red1[8];
    int row = blockIdx.x;
    int t = threadIdx.x;
    const float* xr = x + (size_t)row * DD;
    float4 xv = *(const float4*)(xr + 4*t);
    float sum = xv.x + xv.y + xv.z + xv.w;
    float sq  = xv.x*xv.x + xv.y*xv.y + xv.z*xv.z + xv.w*xv.w;
#pragma unroll
    for (int o = 16; o; o >>= 1) {
        sum += __shfl_xor_sync(0xffffffffu, sum, o);
        sq  += __shfl_xor_sync(0xffffffffu, sq,  o);
    }
    if ((t & 31) == 0) { red0[t >> 5] = sum; red1[t >> 5] = sq; }
    __syncthreads();
    if (t < 32) {
        float s = (t < 8) ? red0[t] : 0.f;
        float q = (t < 8) ? red1[t] : 0.f;
#pragma unroll
        for (int o = 4; o; o >>= 1) {
            s += __shfl_xor_sync(0xffffffffu, s, o);
            q += __shfl_xor_sync(0xffffffffu, q, o);
        }
        if (t == 0) { red0[0] = s; red1[0] = q; }
    }
    __syncthreads();
    float mean = red0[0] * (1.f / (float)DD);
    float var  = red1[0] * (1.f / (float)DD) - mean*mean;
    float rstd = rsqrtf(var + EPS);
    float4 gv = *(const float4*)(gamma + 4*t);
    float4 bv = *(const float4*)(beta + 4*t);
    float v0 = (xv.x - mean) * rstd * gv.x + bv.x;
    float v1 = (xv.y - mean) * rstd * gv.y + bv.y;
    float v2 = (xv.z - mean) * rstd * gv.z + bv.z;
    float v3 = (xv.w - mean) * rstd * gv.w + bv.w;
    __half2 h01 = __floats2half2_rn(v0, v1);
    __half2 h23 = __floats2half2_rn(v2, v3);
    __half2 l01 = __floats2half2_rn(v0 - __half2float(__low2half(h01)),
                                    v1 - __half2float(__high2half(h01)));
    __half2 l23 = __floats2half2_rn(v2 - __half2float(__low2half(h23)),
                                    v3 - __half2float(__high2half(h23)));
    size_t base = (size_t)row * DD + 4*t;
    uint2 hp = make_uint2(*reinterpret_cast<uint32_t*>(&h01), *reinterpret_cast<uint32_t*>(&h23));
    uint2 lp = make_uint2(*reinterpret_cast<uint32_t*>(&l01), *reinterpret_cast<uint32_t*>(&l23));
    *reinterpret_cast<uint2*>(oh + base) = hp;
    *reinterpret_cast<uint2*>(ol + base) = lp;
}

// ---------------- merged weight transpose -> fp16 (all 6 weights) ------------
__global__ void tconv_all(const float* __restrict__ wq, const float* __restrict__ wk,
                          const float* __restrict__ wv, const float* __restrict__ wo,
                          const float* __restrict__ w1, const float* __restrict__ w2,
                          __half* __restrict__ wqkvt, __half* __restrict__ wot,
                          __half* __restrict__ w1t,   __half* __restrict__ w2t)
{
    __shared__ float t[32][33];
    int bid = blockIdx.x;
    const float* W; __half* Th;
    int K, N, tile;
    if (bid < 4096) {
        int w = bid >> 10; tile = bid & 1023;
        K = DD; N = DD;
        if (w == 0)      { W = wq; Th = wqkvt; }
        else if (w == 1) { W = wk; Th = wqkvt + DD*DD; }
        else if (w == 2) { W = wv; Th = wqkvt + 2*DD*DD; }
        else             { W = wo; Th = wot; }
    } else if (bid < 8192) {
        tile = bid - 4096; K = DD; N = MM;
        W = w1; Th = w1t;
    } else {
        tile = bid - 8192; K = MM; N = DD;
        W = w2; Th = w2t;
    }
    int ntx = N >> 5;
    int n0 = (tile % ntx) * 32, k0 = (tile / ntx) * 32;
    int tx = threadIdx.x, ty = threadIdx.y;
#pragma unroll
    for (int j = 0; j < 32; j += 8)
        t[ty + j][tx] = W[(size_t)(k0 + ty + j) * N + n0 + tx];
    __syncthreads();
#pragma unroll
    for (int j = 0; j < 32; j += 8) {
        float v = t[tx][ty + j];
        size_t o = (size_t)(n0 + ty + j) * K + k0 + tx;
        Th[o] = __float2half(v);
    }
}

// ---------------- shared GEMM machinery (fp16 2-term, 3-stage) ----------------
struct GemmAcc { float a[2][4][4]; };

__device__ __forceinline__ void gemm_mainloop(
    uint32_t sb, int tid, int wid, int lane,
    const __half* Ahb, const __half* Alb, const __half* Bhb,
    int Kdim, GemmAcc& acc)
{
    int nch = Kdim / BKH;
    int wm = (wid & 3) * 32;
    int wn = (wid >> 2) * 32;

    auto load_chunk = [&](int c, int s) {
        int k0 = c * BKH;
        uint32_t st = sb + s * STAGE_H;
#pragma unroll
        for (int i = tid; i < 512; i += 256) {
            int row = i >> 2, seg = i & 3;
            uint32_t so = st + row * LDSROW + GSWZ(row, seg) * 16;
            size_t go = (size_t)row * Kdim + k0 + seg * 8;
            cp16(so,           Ahb + go);
            cp16(so + TILEA,   Alb + go);
            if (i < 256) {
                uint32_t sob = st + 2*TILEA + row * LDSROW + GSWZ(row, seg) * 16;
                cp16(sob, Bhb + go);
            }
        }
    };

    load_chunk(0, 0);
    cp_commit();
    load_chunk(1, 1);
    cp_commit();

    for (int c = 0; c < nch; c++) {
        int s = c % 3;
        cp_wait1();
        __syncthreads();
        if (c + 2 < nch) load_chunk(c + 2, (c + 2) % 3);
        cp_commit();

        uint32_t st = sb + s * STAGE_H;
#pragma unroll
        for (int ks = 0; ks < 2; ks++) {
            int colb = ks * 16 + (lane >> 4) * 8;
            uint32_t ah[2][4], al[2][4];
#pragma unroll
            for (int mf = 0; mf < 2; mf++) {
                int r = wm + mf * 16 + (lane & 15);
                uint32_t ad = st + r * LDSROW + GSWZ(r, colb >> 3) * 16;
                ldmx4(ah[mf], ad);
                ldmx4(al[mf], ad + TILEA);
            }
#pragma unroll
            for (int nf2 = 0; nf2 < 2; nf2++) {
                int r = wn + nf2 * 16 + ((lane >> 3) & 1) * 8 + (lane & 7);
                uint32_t bd = st + 2*TILEA + r * LDSROW + GSWZ(r, colb >> 3) * 16;
                uint32_t tb[4], bh0[2], bh1[2];
                ldmx4(tb, bd);
                bh0[0] = tb[0]; bh0[1] = tb[2]; bh1[0] = tb[1]; bh1[1] = tb[3];
#pragma unroll
                for (int mf = 0; mf < 2; mf++) {
                    mma_fp16(acc.a[mf][nf2*2],   ah[mf], bh0);
                    mma_fp16(acc.a[mf][nf2*2],   al[mf], bh0);
                    mma_fp16(acc.a[mf][nf2*2+1], ah[mf], bh1);
                    mma_fp16(acc.a[mf][nf2*2+1], al[mf], bh1);
                }
            }
        }
    }
}

// ---------------- generic GEMM kernel ----------------------------------------
// modes: 1 C=acc+resid; 2 Oh/Ol=split_fp16(gelu(acc+bias)); 3 C=acc+bias+resid
__global__ __launch_bounds__(256, 3)
void gemm_hmma(const __half* __restrict__ Ah, const __half* __restrict__ Al,
               const __half* __restrict__ Bh,
               float* __restrict__ C, int Ndim, int Kdim,
               const float* __restrict__ bias, const float* __restrict__ resid,
               __half* __restrict__ Oh, __half* __restrict__ Ol,
               int mode)
{
    extern __shared__ char hs[];
    uint32_t sb = smem_to_u32(hs);
    int tid = threadIdx.x, wid = tid >> 5, lane = tid & 31;
    int bx = blockIdx.x, by = blockIdx.y;

    GemmAcc acc;
#pragma unroll
    for (int i = 0; i < 2; i++)
#pragma unroll
        for (int j = 0; j < 4; j++)
#pragma unroll
            for (int r = 0; r < 4; r++) acc.a[i][j][r] = 0.f;

    gemm_mainloop(sb, tid, wid, lane,
                  Ah + (size_t)by * BMH * Kdim, Al + (size_t)by * BMH * Kdim,
                  Bh + (size_t)bx * BNH * Kdim, Kdim, acc);

    int wm = (wid & 3) * 32, wn = (wid >> 2) * 32;
    int g = lane >> 2, qd = lane & 3;
#pragma unroll
    for (int mf = 0; mf < 2; mf++) {
#pragma unroll
        for (int half = 0; half < 2; half++) {
            int grow = by * BMH + wm + mf * 16 + g + half * 8;
#pragma unroll
            for (int nf = 0; nf < 4; nf++) {
                int gcol = bx * BNH + wn + nf * 8 + qd * 2;
                float v0 = acc.a[mf][nf][half*2 + 0];
                float v1 = acc.a[mf][nf][half*2 + 1];
                size_t o = (size_t)grow * Ndim + gcol;
                if (mode == 1) {
                    C[o] = v0 + resid[o]; C[o+1] = v1 + resid[o+1];
                } else if (mode == 2) {
                    float g0 = gelu_f(v0 + bias[gcol]);
                    float g1 = gelu_f(v1 + bias[gcol+1]);
                    __half hh, ll;
                    split_fp16(g0, hh, ll); Oh[o] = hh; Ol[o] = ll;
                    split_fp16(g1, hh, ll); Oh[o+1] = hh; Ol[o+1] = ll;
                } else {
                    C[o]   = v0 + bias[gcol]   + resid[o];
                    C[o+1] = v1 + bias[gcol+1] + resid[o+1];
                }
            }
        }
    }
}

// ---------------- fused QKV GEMM with in-register RoPE -----------------------
// W: stacked [3*DD][DD] fp16. bx in [0,48): mat = bx>>4, bn = bx&15.
// q: rope+scale -> fp16 hi/lo; k: rope -> single fp16; v -> fp16 hi/lo.
__global__ __launch_bounds__(256, 3)
void gemm_qkv(const __half* __restrict__ Ah, const __half* __restrict__ Al,
              const __half* __restrict__ Wh,
              const float* __restrict__ rope,
              __half* __restrict__ qh, __half* __restrict__ ql,
              __half* __restrict__ kh,
              __half* __restrict__ vh, __half* __restrict__ vl)
{
    extern __shared__ char hs[];
    uint32_t sb = smem_to_u32(hs);
    int tid = threadIdx.x, wid = tid >> 5, lane = tid & 31;
    int bx = blockIdx.x, by = blockIdx.y;
    int mat = bx >> 4, bn = bx & 15;

    GemmAcc acc;
#pragma unroll
    for (int i = 0; i < 2; i++)
#pragma unroll
        for (int j = 0; j < 4; j++)
#pragma unroll
            for (int r = 0; r < 4; r++) acc.a[i][j][r] = 0.f;

    size_t woff = ((size_t)mat * DD + (size_t)bn * BNH) * DD;
    gemm_mainloop(sb, tid, wid, lane,
                  Ah + (size_t)by * BMH * DD, Al + (size_t)by * BMH * DD,
                  Wh + woff, DD, acc);

    int wm = (wid & 3) * 32, wn = (wid >> 2) * 32;
    int g = lane >> 2, qd = lane & 3;
#pragma unroll
    for (int mf = 0; mf < 2; mf++) {
#pragma unroll
        for (int half = 0; half < 2; half++) {
            int grow = by * BMH + wm + mf * 16 + g + half * 8;
            int srow = grow & (SS - 1);
#pragma unroll
            for (int nf = 0; nf < 4; nf++) {
                int gcol = bn * BNH + wn + nf * 8 + qd * 2;
                float v0 = acc.a[mf][nf][half*2 + 0];
                float v1 = acc.a[mf][nf][half*2 + 1];
                size_t o = (size_t)grow * DD + gcol;
                if (mat == 0) {
                    int i2 = gcol & 63;
                    float2 cs = *(const float2*)(rope + (size_t)srow * 64 + i2);
                    float r0 = (v0 * cs.x - v1 * cs.y) * 0.125f;
                    float r1 = (v0 * cs.y + v1 * cs.x) * 0.125f;
                    __half hh, ll;
                    split_fp16(r0, hh, ll); qh[o] = hh; ql[o] = ll;
                    split_fp16(r1, hh, ll); qh[o+1] = hh; ql[o+1] = ll;
                } else if (mat == 1) {
                    int i2 = gcol & 63;
                    float2 cs = *(const float2*)(rope + (size_t)srow * 64 + i2);
                    float r0 = v0 * cs.x - v1 * cs.y;
                    float r1 = v0 * cs.y + v1 * cs.x;
                    kh[o]   = __float2half(r0);
                    kh[o+1] = __float2half(r1);
                } else {
                    __half hh, ll;
                    split_fp16(v0, hh, ll); vh[o] = hh; vl[o] = ll;
                    split_fp16(v1, hh, ll); vh[o+1] = hh; vl[o+1] = ll;
                }
            }
        }
    }
}

// ---------------- fp16 flash attention (Q2/K1/P1/V2, 3-stage, Q-region reuse)
// SMEM: [0,16384) Qh, [16384,32768) Ql -- becomes K/V stage after t==0.
// Stage offsets {32768, 57344, 0}; within stage: Kh +0, Vh +8192, Vl +16384.
__global__ __launch_bounds__(256, 2)
void flash_attn_hmma(const __half* __restrict__ qh, const __half* __restrict__ ql,
                     const __half* __restrict__ kh,
                     const __half* __restrict__ vh, const __half* __restrict__ vl,
                     __half* __restrict__ ctx_hi, __half* __restrict__ ctx_lo)
{
    extern __shared__ char fs[];
    uint32_t sb = smem_to_u32(fs);
    int tid = threadIdx.x, wid = tid >> 5, lane = tid & 31;
    int g = lane >> 2, qd = lane & 3;
    int qt = blockIdx.x, bh = blockIdx.y;
    int b = bh >> 4, h = bh & 15;
    int q0 = qt * AQT;

    const __half* qhb = qh + ((size_t)(b*SS + q0)) * DD + h * DHH;
    const __half* qlb = ql + ((size_t)(b*SS + q0)) * DD + h * DHH;
    const __half* khb = kh + ((size_t)(b*SS)) * DD + h * DHH;
    const __half* vhb = vh + ((size_t)(b*SS)) * DD + h * DHH;
    const __half* vlb = vl + ((size_t)(b*SS)) * DD + h * DHH;

    auto stage_off = [](int t) -> uint32_t {
        int m = t % 3;
        return (m == 0) ? (uint32_t)AST1 : (m == 1) ? (uint32_t)AST2 : 0u;
    };

    // K/V tile: 3 matrices (Kh,Vh,Vl) x 64 rows x 8 segs = 1536 cp16
    auto load_tile = [&](int t) {
        uint32_t st = sb + stage_off(t);
        const __half* srcs[3] = {khb, vhb, vlb};
#pragma unroll
        for (int i = tid; i < 1536; i += 256) {
            int mtx = i / 512;
            int j = i & 511;
            int row = j >> 3, seg = j & 7;
            uint32_t so = st + mtx * AMAT + row * 128 + ASWZ(row, seg) * 16;
            cp16(so, srcs[mtx] + (size_t)(t*AKT + row) * DD + seg * 8);
        }
    };

    // Q tile: 2 matrices x 128 rows x 8 segs
#pragma unroll
    for (int i = tid; i < 2048; i += 256) {
        int mtx = i >> 10;
        int j = i & 1023;
        int row = j >> 3, seg = j & 7;
        uint32_t so = sb + mtx * 16384 + row * 128 + ASWZ(row, seg) * 16;
        const __half* src = (mtx ? qlb : qhb) + (size_t)row * DD + seg * 8;
        cp16(so, src);
    }
    load_tile(0);
    cp_commit();
    load_tile(1);
    cp_commit();

    float oacc[8][4];
#pragma unroll
    for (int i = 0; i < 8; i++)
#pragma unroll
        for (int j = 0; j < 4; j++) oacc[i][j] = 0.f;
    float m0 = -INFINITY, m1 = -INFINITY, l0 = 0.f, l1 = 0.f;
    uint32_t qfh[4][4], qfl[4][4];

    int ntiles = SS / AKT;   // 32
    for (int t = 0; t < ntiles; t++) {
        uint32_t stb = sb + stage_off(t);
        cp_wait1();
        __syncthreads();

        if (t == 0) {
#pragma unroll
            for (int ks = 0; ks < 4; ks++) {
                int r = wid * 16 + (lane & 15);
                int ch = ks * 2 + (lane >> 4);
                uint32_t ad = sb + r * 128 + ASWZ(r, ch) * 16;
                ldmx4(qfh[ks], ad);
                ldmx4(qfl[ks], ad + 16384);
            }
            __syncthreads();   // all warps done reading Q before stage-2 overwrites
        }

        if (t + 2 < ntiles) load_tile(t + 2);
        cp_commit();

        // ---- S = Q K^T (Q 2-term, K 1-term) ----
        float sacc[8][4];
#pragma unroll
        for (int i = 0; i < 8; i++)
#pragma unroll
            for (int j = 0; j < 4; j++) sacc[i][j] = 0.f;
#pragma unroll
        for (int ks = 0; ks < 4; ks++) {
#pragma unroll
            for (int nf2 = 0; nf2 < 4; nf2++) {
                int r = nf2 * 16 + ((lane >> 3) & 1) * 8 + (lane & 7);
                int ch = ks * 2 + (lane >> 4);
                uint32_t ad = stb + r * 128 + ASWZ(r, ch) * 16;
                uint32_t tb[4], kh0[2], kh1[2];
                ldmx4(tb, ad);
                kh0[0] = tb[0]; kh0[1] = tb[2]; kh1[0] = tb[1]; kh1[1] = tb[3];
                mma_fp16(sacc[nf2*2],   qfh[ks], kh0);
                mma_fp16(sacc[nf2*2],   qfl[ks], kh0);
                mma_fp16(sacc[nf2*2+1], qfh[ks], kh1);
                mma_fp16(sacc[nf2*2+1], qfl[ks], kh1);
            }
        }

        // ---- online softmax on fragments ----
        float mx0 = -INFINITY, mx1 = -INFINITY;
#pragma unroll
        for (int nf = 0; nf < 8; nf++) {
            mx0 = fmaxf(mx0, fmaxf(sacc[nf][0], sacc[nf][1]));
            mx1 = fmaxf(mx1, fmaxf(sacc[nf][2], sacc[nf][3]));
        }
        mx0 = fmaxf(mx0, __shfl_xor_sync(0xffffffffu, mx0, 1));
        mx0 = fmaxf(mx0, __shfl_xor_sync(0xffffffffu, mx0, 2));
        mx1 = fmaxf(mx1, __shfl_xor_sync(0xffffffffu, mx1, 1));
        mx1 = fmaxf(mx1, __shfl_xor_sync(0xffffffffu, mx1, 2));
        float mnew0 = fmaxf(m0, mx0), mnew1 = fmaxf(m1, mx1);
        float corr0 = __expf(m0 - mnew0), corr1 = __expf(m1 - mnew1);

        uint32_t ph[4][4];
        float ps0 = 0.f, ps1 = 0.f;
#pragma unroll
        for (int nf = 0; nf < 8; nf++) {
            float p0 = __expf(sacc[nf][0] - mnew0);
            float p1 = __expf(sacc[nf][1] - mnew0);
            float p2 = __expf(sacc[nf][2] - mnew1);
            float p3 = __expf(sacc[nf][3] - mnew1);
            ps0 += p0 + p1; ps1 += p2 + p3;
            int kks = nf >> 1, hf = nf & 1;
            ph[kks][hf*2 + 0] = pack_h2(p0, p1);
            ph[kks][hf*2 + 1] = pack_h2(p2, p3);
        }
        ps0 += __shfl_xor_sync(0xffffffffu, ps0, 1);
        ps0 += __shfl_xor_sync(0xffffffffu, ps0, 2);
        ps1 += __shfl_xor_sync(0xffffffffu, ps1, 1);
        ps1 += __shfl_xor_sync(0xffffffffu, ps1, 2);
        l0 = l0 * corr0 + ps0;
        l1 = l1 * corr1 + ps1;
        m0 = mnew0; m1 = mnew1;
#pragma unroll
        for (int nf = 0; nf < 8; nf++) {
            oacc[nf][0] *= corr0; oacc[nf][1] *= corr0;
            oacc[nf][2] *= corr1; oacc[nf][3] *= corr1;
        }

        // ---- O += P V (P 1-term, V 2-term) ----
#pragma unroll
        for (int kks = 0; kks < 4; kks++) {
#pragma unroll
            for (int nf2 = 0; nf2 < 4; nf2++) {
                int r = kks * 16 + (lane & 15);
                int ch = nf2 * 2 + (lane >> 4);
                uint32_t vd = stb + AMAT + r * 128 + ASWZ(r, ch) * 16;
                uint32_t tb[4], vh0[2], vh1[2], vl0[2], vl1[2];
                ldmx4t(tb, vd);
                vh0[0] = tb[0]; vh0[1] = tb[1]; vh1[0] = tb[2]; vh1[1] = tb[3];
                ldmx4t(tb, vd + AMAT);
                vl0[0] = tb[0]; vl0[1] = tb[1]; vl1[0] = tb[2]; vl1[1] = tb[3];
                mma_fp16(oacc[nf2*2],   ph[kks], vh0);
                mma_fp16(oacc[nf2*2],   ph[kks], vl0);
                mma_fp16(oacc[nf2*2+1], ph[kks], vh1);
                mma_fp16(oacc[nf2*2+1], ph[kks], vl1);
            }
        }
    }

    // ---- epilogue: fp16 hi/lo ----
    float inv0 = 1.f / l0, inv1 = 1.f / l1;
    size_t row0 = (size_t)(b*SS + q0 + wid*16 + g);
    size_t row1 = row0 + 8;
#pragma unroll
    for (int nf = 0; nf < 8; nf++) {
        int col = h * DHH + nf * 8 + 2 * qd;
        float v00 = oacc[nf][0] * inv0, v01 = oacc[nf][1] * inv0;
        float v10 = oacc[nf][2] * inv1, v11 = oacc[nf][3] * inv1;
        __half2 hi01 = __floats2half2_rn(v00, v01);
        __half2 lo01 = __floats2half2_rn(v00 - __half2float(__low2half(hi01)),
                                         v01 - __half2float(__high2half(hi01)));
        __half2 hi23 = __floats2half2_rn(v10, v11);
        __half2 lo23 = __floats2half2_rn(v10 - __half2float(__low2half(hi23)),
                                         v11 - __half2float(__high2half(hi23)));
        *reinterpret_cast<__half2*>(ctx_hi + row0*DD + col) = hi01;
        *reinterpret_cast<__half2*>(ctx_lo + row0*DD + col) = lo01;
        *reinterpret_cast<__half2*>(ctx_hi + row1*DD + col) = hi23;
        *reinterpret_cast<__half2*>(ctx_lo + row1*DD + col) = lo23;
    }
}

// ---------------- launch ----------------------------------------------------
extern "C" void kernel_launch(void* const* d_in, const int* in_sizes, int n_in,
                              void* d_out, int out_size)
{
    (void)in_sizes; (void)n_in; (void)out_size;
    const float* x     = (const float*)d_in[0];
    const float* ln1_s = (const float*)d_in[1];
    const float* ln1_b = (const float*)d_in[2];
    const float* wk    = (const float*)d_in[3];
    const float* wq    = (const float*)d_in[4];
    const float* wv    = (const float*)d_in[5];
    const float* wo    = (const float*)d_in[6];
    const float* ln2_s = (const float*)d_in[7];
    const float* ln2_b = (const float*)d_in[8];
    const float* w1    = (const float*)d_in[9];
    const float* b1    = (const float*)d_in[10];
    const float* w2    = (const float*)d_in[11];
    const float* b2    = (const float*)d_in[12];
    float* out = (float*)d_out;

    static int configured = 0;
    if (!configured) {
        cudaFuncSetAttribute(gemm_hmma, cudaFuncAttributeMaxDynamicSharedMemorySize, HSMEM);
        cudaFuncSetAttribute(gemm_qkv,  cudaFuncAttributeMaxDynamicSharedMemorySize, HSMEM);
        cudaFuncSetAttribute(flash_attn_hmma, cudaFuncAttributeMaxDynamicSharedMemorySize, ASMEM);
        configured = 1;
    }

    __half *h_hi, *h_lo, *ctx_hi, *ctx_lo, *h2_hi, *h2_lo, *mid_hi, *mid_lo;
    __half *qhp, *qlp, *khp, *vhp, *vlp;
    __half *wqkvt, *wot, *w1t, *w2t;
    float *mlpin, *rope;
    cudaGetSymbolAddress((void**)&h_hi,  g_h_hi);   cudaGetSymbolAddress((void**)&h_lo,  g_h_lo);
    cudaGetSymbolAddress((void**)&qhp,   g_qh);     cudaGetSymbolAddress((void**)&qlp,   g_ql);
    cudaGetSymbolAddress((void**)&khp,   g_kh);
    cudaGetSymbolAddress((void**)&vhp,   g_vh);     cudaGetSymbolAddress((void**)&vlp,   g_vl);
    cudaGetSymbolAddress((void**)&ctx_hi,g_ctx_hi); cudaGetSymbolAddress((void**)&ctx_lo,g_ctx_lo);
    cudaGetSymbolAddress((void**)&mlpin, g_mlpin);
    cudaGetSymbolAddress((void**)&rope,  g_rope);
    cudaGetSymbolAddress((void**)&h2_hi, g_h2_hi);  cudaGetSymbolAddress((void**)&h2_lo, g_h2_lo);
    cudaGetSymbolAddress((void**)&mid_hi,g_mid_hi); cudaGetSymbolAddress((void**)&mid_lo,g_mid_lo);
    cudaGetSymbolAddress((void**)&wqkvt, g_wqkvt);
    cudaGetSymbolAddress((void**)&wot,   g_wot);
    cudaGetSymbolAddress((void**)&w1t,   g_w1t);
    cudaGetSymbolAddress((void**)&w2t,   g_w2t);

    rope_tab<<<(SS*32)/256, 256>>>(rope);
    tconv_all<<<12288, dim3(32, 8)>>>(wq, wk, wv, wo, w1, w2, wqkvt, wot, w1t, w2t);

    // 1. LN1 -> fp16 hi/lo
    ln_fp16<<<ROWS, 256>>>(x, ln1_s, ln1_b, h_hi, h_lo);

    // 2. fused QKV projection + RoPE (q fp16 hi/lo, k fp16 single, v fp16 hi/lo)
    gemm_qkv<<<dim3(48, ROWS/BMH), 256, HSMEM>>>(h_hi, h_lo, wqkvt, rope,
                                                 qhp, qlp, khp, vhp, vlp);

    // 3. fp16 flash attention -> ctx fp16 hi/lo
    flash_attn_hmma<<<dim3(SS/AQT, BB*HH), 256, ASMEM>>>(qhp, qlp, khp, vhp, vlp,
                                                         ctx_hi, ctx_lo);

    // 4. WO projection + residual x -> mlpin (fp32)
    gemm_hmma<<<dim3(DD/BNH, ROWS/BMH), 256, HSMEM>>>(ctx_hi, ctx_lo, wot, mlpin, DD, DD,
                                   nullptr, x, nullptr, nullptr, 1);

    // 5. LN2 -> fp16 hi/lo
    ln_fp16<<<ROWS, 256>>>(mlpin, ln2_s, ln2_b, h2_hi, h2_lo);

    // 6. MLP up: gelu(h2@w1+b1) -> mid fp16 hi/lo
    gemm_hmma<<<dim3(MM/BNH, ROWS/BMH), 256, HSMEM>>>(h2_hi, h2_lo, w1t,
                                   nullptr, MM, DD, b1, nullptr, mid_hi, mid_lo, 2);

    // 7. MLP down + bias + residual -> out (fp32)
    gemm_hmma<<<dim3(DD/BNH, ROWS/BMH), 256, HSMEM>>>(mid_hi, mid_lo, w2t, out, DD, MM,
                                   b2, mlpin, nullptr, nullptr, 3);
}